// round 6
// baseline (speedup 1.0000x reference)
#include <cuda_runtime.h>
#include <cuda_bf16.h>
#include <math.h>
#include <stdint.h>

// Problem constants
#define LT   110592
#define CD   96
#define NS   2304
#define DA   1536
#define NHD  3
#define HIDD 384
#define QK_SCALE 0.17677669529663687f

// Scratch (device globals; alloc APIs banned)
__device__ __nv_bfloat16 g_ln1b[(size_t)LT * CD];
__device__ __nv_bfloat16 g_qkvb[(size_t)LT * 3 * CD];
__device__ float         g_S   [(size_t)NHD * NS * NS];
__device__ __nv_bfloat16 g_Pb  [(size_t)NHD * NS * NS];
__device__ __nv_bfloat16 g_Ob  [(size_t)NS * NHD * DA];
__device__ float         g_x2  [(size_t)LT * CD];
__device__ __nv_bfloat16 g_ln2b[(size_t)LT * CD];
__device__ __nv_bfloat16 g_hidb[(size_t)LT * HIDD];
__device__ __nv_bfloat16 g_wall[110592];

#define W_QKV  0
#define W_PROJ (3 * CD * CD)
#define W_FC1  (W_PROJ + CD * CD)
#define W_FC2  (W_FC1 + HIDD * CD)
#define W_TOT  (W_FC2 + CD * HIDD)

// ---------------------------------------------------------------------------
__device__ __forceinline__ uint32_t s2u(const void* p) {
    return (uint32_t)__cvta_generic_to_shared(p);
}
__device__ __forceinline__ void ldsm4(uint32_t& r0, uint32_t& r1, uint32_t& r2, uint32_t& r3, uint32_t a) {
    asm volatile("ldmatrix.sync.aligned.m8n8.x4.shared.b16 {%0,%1,%2,%3}, [%4];\n"
                 : "=r"(r0), "=r"(r1), "=r"(r2), "=r"(r3) : "r"(a));
}
__device__ __forceinline__ void ldsm4t(uint32_t& r0, uint32_t& r1, uint32_t& r2, uint32_t& r3, uint32_t a) {
    asm volatile("ldmatrix.sync.aligned.m8n8.x4.trans.shared.b16 {%0,%1,%2,%3}, [%4];\n"
                 : "=r"(r0), "=r"(r1), "=r"(r2), "=r"(r3) : "r"(a));
}
__device__ __forceinline__ void mma16816(float* c, const uint32_t* a, const uint32_t* b) {
    asm volatile("mma.sync.aligned.m16n8k16.row.col.f32.bf16.bf16.f32 "
                 "{%0,%1,%2,%3}, {%4,%5,%6,%7}, {%8,%9}, {%0,%1,%2,%3};\n"
                 : "+f"(c[0]), "+f"(c[1]), "+f"(c[2]), "+f"(c[3])
                 : "r"(a[0]), "r"(a[1]), "r"(a[2]), "r"(a[3]), "r"(b[0]), "r"(b[1]));
}
__device__ __forceinline__ void cpa16(uint32_t dst, const void* src) {
    asm volatile("cp.async.cg.shared.global [%0], [%1], 16;\n" :: "r"(dst), "l"(src));
}
__device__ __forceinline__ void cpa_commit() {
    asm volatile("cp.async.commit_group;\n" ::: "memory");
}
__device__ __forceinline__ void cpa_wait2() {
    asm volatile("cp.async.wait_group 2;\n" ::: "memory");
}

// ---------------------------------------------------------------------------
__global__ void ln_kernel(const float* __restrict__ x, const float* __restrict__ g,
                          const float* __restrict__ b, __nv_bfloat16* __restrict__ out) {
    int wid  = (blockIdx.x * blockDim.x + threadIdx.x) >> 5;
    int lane = threadIdx.x & 31;
    if (wid >= LT) return;
    const float* row = x + (size_t)wid * CD;
    float v0 = row[lane], v1 = row[lane + 32], v2 = row[lane + 64];
    float s = v0 + v1 + v2;
    #pragma unroll
    for (int o = 16; o > 0; o >>= 1) s += __shfl_xor_sync(0xffffffffu, s, o);
    float mean = s * (1.0f / 96.0f);
    float d0 = v0 - mean, d1 = v1 - mean, d2 = v2 - mean;
    float vs = d0 * d0 + d1 * d1 + d2 * d2;
    #pragma unroll
    for (int o = 16; o > 0; o >>= 1) vs += __shfl_xor_sync(0xffffffffu, vs, o);
    float rstd = rsqrtf(vs * (1.0f / 96.0f) + 1e-5f);
    __nv_bfloat16* orow = out + (size_t)wid * CD;
    orow[lane]      = __float2bfloat16(d0 * rstd * g[lane]      + b[lane]);
    orow[lane + 32] = __float2bfloat16(d1 * rstd * g[lane + 32] + b[lane + 32]);
    orow[lane + 64] = __float2bfloat16(d2 * rstd * g[lane + 64] + b[lane + 64]);
}

__global__ void f2bf_all(const float* __restrict__ qkv, const float* __restrict__ proj,
                         const float* __restrict__ fc1, const float* __restrict__ fc2,
                         __nv_bfloat16* __restrict__ d) {
    int i = blockIdx.x * blockDim.x + threadIdx.x;
    if (i >= W_TOT) return;
    float v;
    if      (i < W_PROJ) v = qkv[i];
    else if (i < W_FC1)  v = proj[i - W_PROJ];
    else if (i < W_FC2)  v = fc1[i - W_FC1];
    else                 v = fc2[i - W_FC2];
    d[i] = __float2bfloat16(v);
}

// ---------------------------------------------------------------------------
__global__ void softmax_kernel(const float* __restrict__ S, __nv_bfloat16* __restrict__ P) {
    const int row = blockIdx.x;
    const float* p = S + (size_t)row * NS;
    __nv_bfloat16* q = P + (size_t)row * NS;
    const int tid = threadIdx.x;
    __shared__ float sm[8], ss[8];

    float v[9];
    float mx = -3.4e38f;
    #pragma unroll
    for (int i = 0; i < 9; i++) { v[i] = p[tid + 256 * i]; mx = fmaxf(mx, v[i]); }
    #pragma unroll
    for (int o = 16; o > 0; o >>= 1) mx = fmaxf(mx, __shfl_xor_sync(0xffffffffu, mx, o));
    if ((tid & 31) == 0) sm[tid >> 5] = mx;
    __syncthreads();
    mx = sm[0];
    #pragma unroll
    for (int i = 1; i < 8; i++) mx = fmaxf(mx, sm[i]);

    float sum = 0.0f;
    #pragma unroll
    for (int i = 0; i < 9; i++) { v[i] = __expf(v[i] - mx); sum += v[i]; }
    #pragma unroll
    for (int o = 16; o > 0; o >>= 1) sum += __shfl_xor_sync(0xffffffffu, sum, o);
    if ((tid & 31) == 0) ss[tid >> 5] = sum;
    __syncthreads();
    sum = 0.0f;
    #pragma unroll
    for (int i = 0; i < 8; i++) sum += ss[i];
    float inv = 1.0f / sum;
    #pragma unroll
    for (int i = 0; i < 9; i++) q[tid + 256 * i] = __float2bfloat16(v[i] * inv);
}

// ---------------------------------------------------------------------------
// bf16 warp-MMA GEMM, 4-stage cp.async pipeline.
//   C = alpha * A @ op(B) (+ epilogue)
//   BNN=false: B [N,K] (NT) ; BNN=true: B [K,N] (NN)
// EPI: 0 none, 1 +bias, 2 +bias+gelu, 3 +bias+residual ; OBF: bf16 vs fp32 out
// MINB: min blocks/SM for launch bounds (2 for small tiles, 1 for big)
// ---------------------------------------------------------------------------
template<int BM, int BN, bool BNN, int EPI, bool OBF, int MINB>
__global__ void __launch_bounds__(256, MINB) mma_gemm(
    const __nv_bfloat16* __restrict__ A, int lda, long aZ,
    const __nv_bfloat16* __restrict__ B, int ldb, long bZ,
    const float* __restrict__ bias, const float* __restrict__ res,
    void* __restrict__ Cout, int ldc, long cZ, int K, float alpha)
{
    constexpr int BK = 32, SA = BK + 8;
    constexpr int WM = 4, WN = 2;
    constexpr int WMT = BM / WM;         // 32
    constexpr int WNT = BN / WN;         // 48 / 64 / 128
    constexpr int MI = WMT / 16;         // 2
    constexpr int NI = WNT / 8;          // 6 / 8 / 16
    constexpr int THREADS = 256;
    constexpr int BSR = BNN ? BK : BN;
    constexpr int BSC = BNN ? BN + 8 : SA;
    constexpr int STAGE = BM * SA + BSR * BSC;
    constexpr int NSTG = 4;

    extern __shared__ __nv_bfloat16 smp[];

    const int tid  = threadIdx.x;
    const int wid  = tid >> 5;
    const int lane = tid & 31;
    const int wm = wid / WN, wn = wid % WN;
    const int i0 = blockIdx.y * BM;
    const int n0 = blockIdx.x * BN;
    A += (size_t)blockIdx.z * aZ + (size_t)i0 * lda;
    if (!BNN) B += (size_t)blockIdx.z * bZ + (size_t)n0 * ldb;
    else      B += (size_t)blockIdx.z * bZ + n0;

    float c[MI][NI][4];
    #pragma unroll
    for (int mi = 0; mi < MI; mi++)
        #pragma unroll
        for (int ni = 0; ni < NI; ni++)
            #pragma unroll
            for (int e = 0; e < 4; e++) c[mi][ni][e] = 0.0f;

    const int nKT = K / BK;

    auto load_stage = [&](int kt, int st) {
        __nv_bfloat16* As = smp + st * STAGE;
        __nv_bfloat16* Bs = As + BM * SA;
        const __nv_bfloat16* Ag = A + kt * BK;
        #pragma unroll
        for (int e = tid; e < BM * 4; e += THREADS) {
            int m = e >> 2, kv = e & 3;
            cpa16(s2u(As + m * SA + kv * 8), Ag + (size_t)m * lda + kv * 8);
        }
        if (!BNN) {
            const __nv_bfloat16* Bg = B + kt * BK;
            #pragma unroll
            for (int e = tid; e < BN * 4; e += THREADS) {
                int n = e >> 2, kv = e & 3;
                cpa16(s2u(Bs + n * SA + kv * 8), Bg + (size_t)n * ldb + kv * 8);
            }
        } else {
            const __nv_bfloat16* Bg = B + (size_t)kt * BK * ldb;
            #pragma unroll
            for (int e = tid; e < BK * (BN / 8); e += THREADS) {
                int k = e / (BN / 8), nv = e % (BN / 8);
                cpa16(s2u(Bs + k * (BN + 8) + nv * 8), Bg + (size_t)k * ldb + nv * 8);
            }
        }
    };

    load_stage(0, 0); cpa_commit();
    if (nKT > 1) load_stage(1, 1);
    cpa_commit();
    if (nKT > 2) load_stage(2, 2);
    cpa_commit();

    for (int kt = 0; kt < nKT; kt++) {
        cpa_wait2();
        __syncthreads();

        if (kt + 3 < nKT) load_stage(kt + 3, (kt + 3) % NSTG);
        cpa_commit();

        const int st = kt % NSTG;
        __nv_bfloat16* As = smp + st * STAGE;
        __nv_bfloat16* Bs = As + BM * SA;

        #pragma unroll
        for (int kk = 0; kk < 2; kk++) {
            uint32_t a[MI][4];
            #pragma unroll
            for (int mi = 0; mi < MI; mi++) {
                int m  = wm * WMT + mi * 16 + (lane & 15);
                int kc = kk * 16 + (lane >> 4) * 8;
                ldsm4(a[mi][0], a[mi][1], a[mi][2], a[mi][3], s2u(As + m * SA + kc));
            }
            uint32_t b[NI][2];
            #pragma unroll
            for (int np = 0; np < NI / 2; np++) {
                uint32_t r0, r1, r2, r3;
                if (!BNN) {
                    int row = wn * WNT + np * 16 + (lane & 7) + ((lane >> 4) & 1) * 8;
                    int col = kk * 16 + ((lane >> 3) & 1) * 8;
                    ldsm4(r0, r1, r2, r3, s2u(Bs + row * SA + col));
                } else {
                    int row = kk * 16 + (lane & 7) + ((lane >> 3) & 1) * 8;
                    int col = wn * WNT + np * 16 + ((lane >> 4) & 1) * 8;
                    ldsm4t(r0, r1, r2, r3, s2u(Bs + row * (BN + 8) + col));
                }
                b[np * 2][0] = r0; b[np * 2][1] = r1;
                b[np * 2 + 1][0] = r2; b[np * 2 + 1][1] = r3;
            }
            #pragma unroll
            for (int mi = 0; mi < MI; mi++)
                #pragma unroll
                for (int ni = 0; ni < NI; ni++)
                    mma16816(c[mi][ni], a[mi], b[ni]);
        }
    }

    // Epilogue
    float* Cf = (float*)Cout + (size_t)blockIdx.z * cZ;
    __nv_bfloat16* Cb = (__nv_bfloat16*)Cout + (size_t)blockIdx.z * cZ;
    #pragma unroll
    for (int mi = 0; mi < MI; mi++) {
        int rbase = i0 + wm * WMT + mi * 16 + (lane >> 2);
        #pragma unroll
        for (int ni = 0; ni < NI; ni++) {
            int col = n0 + wn * WNT + ni * 8 + (lane & 3) * 2;
            #pragma unroll
            for (int hh = 0; hh < 2; hh++) {
                int r = rbase + hh * 8;
                float v0 = c[mi][ni][hh * 2 + 0] * alpha;
                float v1 = c[mi][ni][hh * 2 + 1] * alpha;
                if (EPI >= 1) { v0 += bias[col]; v1 += bias[col + 1]; }
                if (EPI == 2) {
                    v0 = 0.5f * v0 * (1.0f + erff(v0 * 0.70710678118654752f));
                    v1 = 0.5f * v1 * (1.0f + erff(v1 * 0.70710678118654752f));
                }
                if (EPI == 3) {
                    v0 += res[(size_t)r * ldc + col];
                    v1 += res[(size_t)r * ldc + col + 1];
                }
                if (OBF) {
                    __nv_bfloat162 p;
                    p.x = __float2bfloat16(v0); p.y = __float2bfloat16(v1);
                    *(__nv_bfloat162*)&Cb[(size_t)r * ldc + col] = p;
                } else {
                    float2 p; p.x = v0; p.y = v1;
                    *(float2*)&Cf[(size_t)r * ldc + col] = p;
                }
            }
        }
    }
}

// ---------------------------------------------------------------------------
extern "C" void kernel_launch(void* const* d_in, const int* in_sizes, int n_in,
                              void* d_out, int out_size) {
    const float* x      = (const float*)d_in[0];
    const float* ln1_g  = (const float*)d_in[2];
    const float* ln1_b  = (const float*)d_in[3];
    const float* qkv_w  = (const float*)d_in[4];
    const float* qkv_b  = (const float*)d_in[5];
    const float* proj_w = (const float*)d_in[6];
    const float* proj_b = (const float*)d_in[7];
    const float* ln2_g  = (const float*)d_in[8];
    const float* ln2_b  = (const float*)d_in[9];
    const float* fc1_w  = (const float*)d_in[10];
    const float* fc1_b  = (const float*)d_in[11];
    const float* fc2_w  = (const float*)d_in[12];
    const float* fc2_b  = (const float*)d_in[13];
    float* out = (float*)d_out;

    __nv_bfloat16 *p_ln1, *p_qkv, *p_P, *p_O, *p_ln2, *p_hid, *p_w;
    float *p_S, *p_x2;
    cudaGetSymbolAddress((void**)&p_ln1,  g_ln1b);
    cudaGetSymbolAddress((void**)&p_qkv,  g_qkvb);
    cudaGetSymbolAddress((void**)&p_S,    g_S);
    cudaGetSymbolAddress((void**)&p_P,    g_Pb);
    cudaGetSymbolAddress((void**)&p_O,    g_Ob);
    cudaGetSymbolAddress((void**)&p_x2,   g_x2);
    cudaGetSymbolAddress((void**)&p_ln2,  g_ln2b);
    cudaGetSymbolAddress((void**)&p_hid,  g_hidb);
    cudaGetSymbolAddress((void**)&p_w,    g_wall);

    // dynamic SMEM (bytes), 4 stages
    const int SM_NT96  = 4 * (128 * 40 + 96 * 40) * 2;    // 71680  (dense)
    const int SM_NT256 = 4 * (128 * 40 + 256 * 40) * 2;   // 122880 (QK)
    const int SM_NN256 = 4 * (128 * 40 + 32 * 264) * 2;   // 108544 (PV)
    cudaFuncSetAttribute(mma_gemm<128, 96, false, 1, true, 2>,
                         cudaFuncAttributeMaxDynamicSharedMemorySize, SM_NT96);
    cudaFuncSetAttribute(mma_gemm<128, 256, false, 0, false, 1>,
                         cudaFuncAttributeMaxDynamicSharedMemorySize, SM_NT256);
    cudaFuncSetAttribute(mma_gemm<128, 256, true, 0, true, 1>,
                         cudaFuncAttributeMaxDynamicSharedMemorySize, SM_NN256);
    cudaFuncSetAttribute(mma_gemm<128, 96, false, 3, false, 2>,
                         cudaFuncAttributeMaxDynamicSharedMemorySize, SM_NT96);
    cudaFuncSetAttribute(mma_gemm<128, 96, false, 2, true, 2>,
                         cudaFuncAttributeMaxDynamicSharedMemorySize, SM_NT96);

    f2bf_all<<<(W_TOT + 255)/256, 256>>>(qkv_w, proj_w, fc1_w, fc2_w, p_w);

    // 1. LN1
    ln_kernel<<<LT / 8, 256>>>(x, ln1_g, ln1_b, p_ln1);

    // 2. QKV
    mma_gemm<128, 96, false, 1, true, 2><<<dim3(3, LT / 128, 1), 256, SM_NT96>>>(
        p_ln1, CD, 0, p_w + W_QKV, CD, 0, qkv_b, nullptr, p_qkv, 3 * CD, 0, CD, 1.0f);

    // 3. Logits: S[h] = scale * Q[h] @ K[h]^T  (128x256 tiles)
    mma_gemm<128, 256, false, 0, false, 1><<<dim3(NS / 256, NS / 128, NHD), 256, SM_NT256>>>(
        p_qkv, 3 * CD * 48, DA, p_qkv + 3 * DA, 3 * CD * 48, DA,
        nullptr, nullptr, p_S, NS, (long)NS * NS, DA, QK_SCALE);

    // 4. Softmax
    softmax_kernel<<<NHD * NS, 256>>>(p_S, p_P);

    // 5. O[h] = P[h] @ V[h]  (NN, 128x256 tiles)
    mma_gemm<128, 256, true, 0, true, 1><<<dim3(DA / 256, NS / 128, NHD), 256, SM_NN256>>>(
        p_P, NS, (long)NS * NS, p_qkv + 6 * DA, 3 * CD * 48, DA,
        nullptr, nullptr, p_O, NHD * DA, DA, NS, 1.0f);

    // 6. proj + bias + residual(x)
    mma_gemm<128, 96, false, 3, false, 2><<<dim3(1, LT / 128, 1), 256, SM_NT96>>>(
        p_O, CD, 0, p_w + W_PROJ, CD, 0, proj_b, x, p_x2, CD, 0, CD, 1.0f);

    // 7. LN2
    ln_kernel<<<LT / 8, 256>>>(p_x2, ln2_g, ln2_b, p_ln2);

    // 8. fc1 + bias + GELU
    mma_gemm<128, 96, false, 2, true, 2><<<dim3(HIDD / 96, LT / 128, 1), 256, SM_NT96>>>(
        p_ln2, CD, 0, p_w + W_FC1, CD, 0, fc1_b, nullptr, p_hid, HIDD, 0, CD, 1.0f);

    // 9. fc2 + bias + residual
    mma_gemm<128, 96, false, 3, false, 2><<<dim3(1, LT / 128, 1), 256, SM_NT96>>>(
        p_hid, HIDD, 0, p_w + W_FC2, HIDD, 0, fc2_b, p_x2, out, CD, 0, HIDD, 1.0f);
}

// round 9
// speedup vs baseline: 1.2195x; 1.2195x over previous
#include <cuda_runtime.h>
#include <cuda_bf16.h>
#include <cuda_fp16.h>
#include <math.h>
#include <stdint.h>

// Problem constants
#define LT   110592
#define CD   96
#define NS   2304
#define DA   1536
#define NHD  3
#define HIDD 384
#define QK_SCALE 0.17677669529663687f

// Scratch (device globals; alloc APIs banned)
__device__ __nv_bfloat16 g_ln1b[(size_t)LT * CD];
__device__ __half        g_qkvh[(size_t)LT * 3 * CD];   // fp16 qkv
__device__ float         g_S   [(size_t)NHD * NS * NS];
__device__ __half        g_Ph  [(size_t)NHD * NS * NS]; // fp16 probs
__device__ __nv_bfloat16 g_Ob  [(size_t)NS * NHD * DA];
__device__ float         g_x2  [(size_t)LT * CD];
__device__ __nv_bfloat16 g_ln2b[(size_t)LT * CD];
__device__ __nv_bfloat16 g_hidb[(size_t)LT * HIDD];
__device__ __nv_bfloat16 g_wall[110592];

#define W_QKV  0
#define W_PROJ (3 * CD * CD)
#define W_FC1  (W_PROJ + CD * CD)
#define W_FC2  (W_FC1 + HIDD * CD)
#define W_TOT  (W_FC2 + CD * HIDD)

// ---------------------------------------------------------------------------
__device__ __forceinline__ uint32_t s2u(const void* p) {
    return (uint32_t)__cvta_generic_to_shared(p);
}
__device__ __forceinline__ void ldsm4(uint32_t& r0, uint32_t& r1, uint32_t& r2, uint32_t& r3, uint32_t a) {
    asm volatile("ldmatrix.sync.aligned.m8n8.x4.shared.b16 {%0,%1,%2,%3}, [%4];\n"
                 : "=r"(r0), "=r"(r1), "=r"(r2), "=r"(r3) : "r"(a));
}
__device__ __forceinline__ void ldsm4t(uint32_t& r0, uint32_t& r1, uint32_t& r2, uint32_t& r3, uint32_t a) {
    asm volatile("ldmatrix.sync.aligned.m8n8.x4.trans.shared.b16 {%0,%1,%2,%3}, [%4];\n"
                 : "=r"(r0), "=r"(r1), "=r"(r2), "=r"(r3) : "r"(a));
}
__device__ __forceinline__ void mma16816(float* c, const uint32_t* a, const uint32_t* b) {
    asm volatile("mma.sync.aligned.m16n8k16.row.col.f32.bf16.bf16.f32 "
                 "{%0,%1,%2,%3}, {%4,%5,%6,%7}, {%8,%9}, {%0,%1,%2,%3};\n"
                 : "+f"(c[0]), "+f"(c[1]), "+f"(c[2]), "+f"(c[3])
                 : "r"(a[0]), "r"(a[1]), "r"(a[2]), "r"(a[3]), "r"(b[0]), "r"(b[1]));
}
__device__ __forceinline__ void mma16816h(uint32_t* c, const uint32_t* a, const uint32_t* b) {
    asm volatile("mma.sync.aligned.m16n8k16.row.col.f16.f16.f16.f16 "
                 "{%0,%1}, {%2,%3,%4,%5}, {%6,%7}, {%0,%1};\n"
                 : "+r"(c[0]), "+r"(c[1])
                 : "r"(a[0]), "r"(a[1]), "r"(a[2]), "r"(a[3]), "r"(b[0]), "r"(b[1]));
}
__device__ __forceinline__ void cpa16(uint32_t dst, const void* src) {
    asm volatile("cp.async.cg.shared.global [%0], [%1], 16;\n" :: "r"(dst), "l"(src));
}
__device__ __forceinline__ void cpa_commit() {
    asm volatile("cp.async.commit_group;\n" ::: "memory");
}
__device__ __forceinline__ void cpa_wait2() {
    asm volatile("cp.async.wait_group 2;\n" ::: "memory");
}

// ---------------------------------------------------------------------------
__global__ void ln_kernel(const float* __restrict__ x, const float* __restrict__ g,
                          const float* __restrict__ b, __nv_bfloat16* __restrict__ out) {
    int wid  = (blockIdx.x * blockDim.x + threadIdx.x) >> 5;
    int lane = threadIdx.x & 31;
    if (wid >= LT) return;
    const float* row = x + (size_t)wid * CD;
    float v0 = row[lane], v1 = row[lane + 32], v2 = row[lane + 64];
    float s = v0 + v1 + v2;
    #pragma unroll
    for (int o = 16; o > 0; o >>= 1) s += __shfl_xor_sync(0xffffffffu, s, o);
    float mean = s * (1.0f / 96.0f);
    float d0 = v0 - mean, d1 = v1 - mean, d2 = v2 - mean;
    float vs = d0 * d0 + d1 * d1 + d2 * d2;
    #pragma unroll
    for (int o = 16; o > 0; o >>= 1) vs += __shfl_xor_sync(0xffffffffu, vs, o);
    float rstd = rsqrtf(vs * (1.0f / 96.0f) + 1e-5f);
    __nv_bfloat16* orow = out + (size_t)wid * CD;
    orow[lane]      = __float2bfloat16(d0 * rstd * g[lane]      + b[lane]);
    orow[lane + 32] = __float2bfloat16(d1 * rstd * g[lane + 32] + b[lane + 32]);
    orow[lane + 64] = __float2bfloat16(d2 * rstd * g[lane + 64] + b[lane + 64]);
}

__global__ void f2bf_all(const float* __restrict__ qkv, const float* __restrict__ proj,
                         const float* __restrict__ fc1, const float* __restrict__ fc2,
                         __nv_bfloat16* __restrict__ d) {
    int i = blockIdx.x * blockDim.x + threadIdx.x;
    if (i >= W_TOT) return;
    float v;
    if      (i < W_PROJ) v = qkv[i];
    else if (i < W_FC1)  v = proj[i - W_PROJ];
    else if (i < W_FC2)  v = fc1[i - W_FC1];
    else                 v = fc2[i - W_FC2];
    d[i] = __float2bfloat16(v);
}

// ---------------------------------------------------------------------------
__global__ void softmax_kernel(const float* __restrict__ S, __half* __restrict__ P) {
    const int row = blockIdx.x;
    const float* p = S + (size_t)row * NS;
    __half* q = P + (size_t)row * NS;
    const int tid = threadIdx.x;
    __shared__ float sm[8], ss[8];

    float v[9];
    float mx = -3.4e38f;
    #pragma unroll
    for (int i = 0; i < 9; i++) { v[i] = p[tid + 256 * i]; mx = fmaxf(mx, v[i]); }
    #pragma unroll
    for (int o = 16; o > 0; o >>= 1) mx = fmaxf(mx, __shfl_xor_sync(0xffffffffu, mx, o));
    if ((tid & 31) == 0) sm[tid >> 5] = mx;
    __syncthreads();
    mx = sm[0];
    #pragma unroll
    for (int i = 1; i < 8; i++) mx = fmaxf(mx, sm[i]);

    float sum = 0.0f;
    #pragma unroll
    for (int i = 0; i < 9; i++) { v[i] = __expf(v[i] - mx); sum += v[i]; }
    #pragma unroll
    for (int o = 16; o > 0; o >>= 1) sum += __shfl_xor_sync(0xffffffffu, sum, o);
    if ((tid & 31) == 0) ss[tid >> 5] = sum;
    __syncthreads();
    sum = 0.0f;
    #pragma unroll
    for (int i = 0; i < 8; i++) sum += ss[i];
    float inv = 1.0f / sum;
    #pragma unroll
    for (int i = 0; i < 9; i++) q[tid + 256 * i] = __float2half(v[i] * inv);
}

// ---------------------------------------------------------------------------
// bf16 warp-MMA GEMM (dense layers), 4-stage cp.async, 2 CTAs/SM.
// C = alpha*A@B^T (+epi). OUTM: 0 fp32, 1 bf16, 2 fp16
// EPI: 0 none, 1 +bias, 2 +bias+gelu, 3 +bias+residual
// ---------------------------------------------------------------------------
template<int BM, int BN, int EPI, int OUTM>
__global__ void __launch_bounds__(256, 2) mma_gemm(
    const __nv_bfloat16* __restrict__ A, int lda,
    const __nv_bfloat16* __restrict__ B, int ldb,
    const float* __restrict__ bias, const float* __restrict__ res,
    void* __restrict__ Cout, int ldc, int K, float alpha)
{
    constexpr int BK = 32, SA = BK + 8;
    constexpr int WM = 4, WN = 2;
    constexpr int WMT = BM / WM;
    constexpr int WNT = BN / WN;
    constexpr int MI = WMT / 16;
    constexpr int NI = WNT / 8;
    constexpr int THREADS = 256;
    constexpr int STAGE = BM * SA + BN * SA;
    constexpr int NSTG = 4;

    extern __shared__ __nv_bfloat16 smpb[];

    const int tid  = threadIdx.x;
    const int wid  = tid >> 5;
    const int lane = tid & 31;
    const int wm = wid / WN, wn = wid % WN;
    const int i0 = blockIdx.y * BM;
    const int n0 = blockIdx.x * BN;
    A += (size_t)i0 * lda;
    B += (size_t)n0 * ldb;

    float c[MI][NI][4];
    #pragma unroll
    for (int mi = 0; mi < MI; mi++)
        #pragma unroll
        for (int ni = 0; ni < NI; ni++)
            #pragma unroll
            for (int e = 0; e < 4; e++) c[mi][ni][e] = 0.0f;

    const int nKT = K / BK;

    auto load_stage = [&](int kt, int st) {
        __nv_bfloat16* As = smpb + st * STAGE;
        __nv_bfloat16* Bs = As + BM * SA;
        const __nv_bfloat16* Ag = A + kt * BK;
        #pragma unroll
        for (int e = tid; e < BM * 4; e += THREADS) {
            int m = e >> 2, kv = e & 3;
            cpa16(s2u(As + m * SA + kv * 8), Ag + (size_t)m * lda + kv * 8);
        }
        const __nv_bfloat16* Bg = B + kt * BK;
        #pragma unroll
        for (int e = tid; e < BN * 4; e += THREADS) {
            int n = e >> 2, kv = e & 3;
            cpa16(s2u(Bs + n * SA + kv * 8), Bg + (size_t)n * ldb + kv * 8);
        }
    };

    load_stage(0, 0); cpa_commit();
    if (nKT > 1) load_stage(1, 1);
    cpa_commit();
    if (nKT > 2) load_stage(2, 2);
    cpa_commit();

    for (int kt = 0; kt < nKT; kt++) {
        cpa_wait2();
        __syncthreads();
        if (kt + 3 < nKT) load_stage(kt + 3, (kt + 3) % NSTG);
        cpa_commit();

        const int st = kt % NSTG;
        __nv_bfloat16* As = smpb + st * STAGE;
        __nv_bfloat16* Bs = As + BM * SA;

        #pragma unroll
        for (int kk = 0; kk < 2; kk++) {
            uint32_t a[MI][4];
            #pragma unroll
            for (int mi = 0; mi < MI; mi++) {
                int m  = wm * WMT + mi * 16 + (lane & 15);
                int kc = kk * 16 + (lane >> 4) * 8;
                ldsm4(a[mi][0], a[mi][1], a[mi][2], a[mi][3], s2u(As + m * SA + kc));
            }
            uint32_t b[NI][2];
            #pragma unroll
            for (int np = 0; np < NI / 2; np++) {
                uint32_t r0, r1, r2, r3;
                int row = wn * WNT + np * 16 + (lane & 7) + ((lane >> 4) & 1) * 8;
                int col = kk * 16 + ((lane >> 3) & 1) * 8;
                ldsm4(r0, r1, r2, r3, s2u(Bs + row * SA + col));
                b[np * 2][0] = r0; b[np * 2][1] = r1;
                b[np * 2 + 1][0] = r2; b[np * 2 + 1][1] = r3;
            }
            #pragma unroll
            for (int mi = 0; mi < MI; mi++)
                #pragma unroll
                for (int ni = 0; ni < NI; ni++)
                    mma16816(c[mi][ni], a[mi], b[ni]);
        }
    }

    float* Cf = (float*)Cout;
    __nv_bfloat16* Cb = (__nv_bfloat16*)Cout;
    __half* Ch = (__half*)Cout;
    #pragma unroll
    for (int mi = 0; mi < MI; mi++) {
        int rbase = i0 + wm * WMT + mi * 16 + (lane >> 2);
        #pragma unroll
        for (int ni = 0; ni < NI; ni++) {
            int col = n0 + wn * WNT + ni * 8 + (lane & 3) * 2;
            #pragma unroll
            for (int hh = 0; hh < 2; hh++) {
                int r = rbase + hh * 8;
                float v0 = c[mi][ni][hh * 2 + 0] * alpha;
                float v1 = c[mi][ni][hh * 2 + 1] * alpha;
                if (EPI >= 1) { v0 += bias[col]; v1 += bias[col + 1]; }
                if (EPI == 2) {
                    v0 = 0.5f * v0 * (1.0f + erff(v0 * 0.70710678118654752f));
                    v1 = 0.5f * v1 * (1.0f + erff(v1 * 0.70710678118654752f));
                }
                if (EPI == 3) {
                    v0 += res[(size_t)r * ldc + col];
                    v1 += res[(size_t)r * ldc + col + 1];
                }
                if (OUTM == 0) {
                    float2 p; p.x = v0; p.y = v1;
                    *(float2*)&Cf[(size_t)r * ldc + col] = p;
                } else if (OUTM == 1) {
                    __nv_bfloat162 p;
                    p.x = __float2bfloat16(v0); p.y = __float2bfloat16(v1);
                    *(__nv_bfloat162*)&Cb[(size_t)r * ldc + col] = p;
                } else {
                    __half2 p = __floats2half2_rn(v0, v1);
                    *(__half2*)&Ch[(size_t)r * ldc + col] = p;
                }
            }
        }
    }
}

// ---------------------------------------------------------------------------
// fp16 warp-MMA GEMM (attention), fp16 accumulate, 4-stage cp.async, 2 CTAs/SM.
//   C = alpha * A @ op(B). BNN=false: B [N,K] (NT); BNN=true: B [K,N] (NN)
// OUTM: 0 fp32*alpha, 1 bf16
// ---------------------------------------------------------------------------
template<bool BNN, int OUTM>
__global__ void __launch_bounds__(256, 2) hmma_gemm(
    const __half* __restrict__ A, int lda, long aZ,
    const __half* __restrict__ B, int ldb, long bZ,
    void* __restrict__ Cout, int ldc, long cZ, int K, float alpha)
{
    constexpr int BM = 128, BN = 128;
    constexpr int BK = 32, SA = BK + 8;
    constexpr int WM = 4, WN = 2;
    constexpr int WMT = BM / WM;   // 32
    constexpr int WNT = BN / WN;   // 64
    constexpr int MI = 2, NI = 8;
    constexpr int THREADS = 256;
    constexpr int BSR = BNN ? BK : BN;
    constexpr int BSC = BNN ? BN + 8 : SA;
    constexpr int STAGE = BM * SA + BSR * BSC;
    constexpr int NSTG = 4;

    extern __shared__ __half smph[];

    const int tid  = threadIdx.x;
    const int wid  = tid >> 5;
    const int lane = tid & 31;
    const int wm = wid / WN, wn = wid % WN;
    const int i0 = blockIdx.y * BM;
    const int n0 = blockIdx.x * BN;
    A += (size_t)blockIdx.z * aZ + (size_t)i0 * lda;
    if (!BNN) B += (size_t)blockIdx.z * bZ + (size_t)n0 * ldb;
    else      B += (size_t)blockIdx.z * bZ + n0;

    uint32_t c[MI][NI][2];
    #pragma unroll
    for (int mi = 0; mi < MI; mi++)
        #pragma unroll
        for (int ni = 0; ni < NI; ni++) { c[mi][ni][0] = 0u; c[mi][ni][1] = 0u; }

    const int nKT = K / BK;

    auto load_stage = [&](int kt, int st) {
        __half* As = smph + st * STAGE;
        __half* Bs = As + BM * SA;
        const __half* Ag = A + kt * BK;
        #pragma unroll
        for (int e = tid; e < BM * 4; e += THREADS) {
            int m = e >> 2, kv = e & 3;
            cpa16(s2u(As + m * SA + kv * 8), Ag + (size_t)m * lda + kv * 8);
        }
        if (!BNN) {
            const __half* Bg = B + kt * BK;
            #pragma unroll
            for (int e = tid; e < BN * 4; e += THREADS) {
                int n = e >> 2, kv = e & 3;
                cpa16(s2u(Bs + n * SA + kv * 8), Bg + (size_t)n * ldb + kv * 8);
            }
        } else {
            const __half* Bg = B + (size_t)kt * BK * ldb;
            #pragma unroll
            for (int e = tid; e < BK * (BN / 8); e += THREADS) {
                int k = e / (BN / 8), nv = e % (BN / 8);
                cpa16(s2u(Bs + k * (BN + 8) + nv * 8), Bg + (size_t)k * ldb + nv * 8);
            }
        }
    };

    load_stage(0, 0); cpa_commit();
    if (nKT > 1) load_stage(1, 1);
    cpa_commit();
    if (nKT > 2) load_stage(2, 2);
    cpa_commit();

    for (int kt = 0; kt < nKT; kt++) {
        cpa_wait2();
        __syncthreads();
        if (kt + 3 < nKT) load_stage(kt + 3, (kt + 3) % NSTG);
        cpa_commit();

        const int st = kt % NSTG;
        __half* As = smph + st * STAGE;
        __half* Bs = As + BM * SA;

        #pragma unroll
        for (int kk = 0; kk < 2; kk++) {
            uint32_t a[MI][4];
            #pragma unroll
            for (int mi = 0; mi < MI; mi++) {
                int m  = wm * WMT + mi * 16 + (lane & 15);
                int kc = kk * 16 + (lane >> 4) * 8;
                ldsm4(a[mi][0], a[mi][1], a[mi][2], a[mi][3], s2u(As + m * SA + kc));
            }
            uint32_t b[NI][2];
            #pragma unroll
            for (int np = 0; np < NI / 2; np++) {
                uint32_t r0, r1, r2, r3;
                if (!BNN) {
                    int row = wn * WNT + np * 16 + (lane & 7) + ((lane >> 4) & 1) * 8;
                    int col = kk * 16 + ((lane >> 3) & 1) * 8;
                    ldsm4(r0, r1, r2, r3, s2u(Bs + row * SA + col));
                } else {
                    int row = kk * 16 + (lane & 7) + ((lane >> 3) & 1) * 8;
                    int col = wn * WNT + np * 16 + ((lane >> 4) & 1) * 8;
                    ldsm4t(r0, r1, r2, r3, s2u(Bs + row * (BN + 8) + col));
                }
                b[np * 2][0] = r0; b[np * 2][1] = r1;
                b[np * 2 + 1][0] = r2; b[np * 2 + 1][1] = r3;
            }
            #pragma unroll
            for (int mi = 0; mi < MI; mi++)
                #pragma unroll
                for (int ni = 0; ni < NI; ni++)
                    mma16816h(c[mi][ni], a[mi], b[ni]);
        }
    }

    // Epilogue
    float* Cf = (float*)Cout + (size_t)blockIdx.z * cZ;
    __nv_bfloat16* Cb = (__nv_bfloat16*)Cout + (size_t)blockIdx.z * cZ;
    #pragma unroll
    for (int mi = 0; mi < MI; mi++) {
        int rbase = i0 + wm * WMT + mi * 16 + (lane >> 2);
        #pragma unroll
        for (int ni = 0; ni < NI; ni++) {
            int col = n0 + wn * WNT + ni * 8 + (lane & 3) * 2;
            #pragma unroll
            for (int hh = 0; hh < 2; hh++) {
                int r = rbase + hh * 8;
                __half2 hv = *(__half2*)&c[mi][ni][hh];
                float2 f = __half22float2(hv);
                if (OUTM == 0) {
                    float2 p; p.x = f.x * alpha; p.y = f.y * alpha;
                    *(float2*)&Cf[(size_t)r * ldc + col] = p;
                } else {
                    __nv_bfloat162 p;
                    p.x = __float2bfloat16(f.x); p.y = __float2bfloat16(f.y);
                    *(__nv_bfloat162*)&Cb[(size_t)r * ldc + col] = p;
                }
            }
        }
    }
}

// ---------------------------------------------------------------------------
extern "C" void kernel_launch(void* const* d_in, const int* in_sizes, int n_in,
                              void* d_out, int out_size) {
    const float* x      = (const float*)d_in[0];
    const float* ln1_g  = (const float*)d_in[2];
    const float* ln1_b  = (const float*)d_in[3];
    const float* qkv_w  = (const float*)d_in[4];
    const float* qkv_b  = (const float*)d_in[5];
    const float* proj_w = (const float*)d_in[6];
    const float* proj_b = (const float*)d_in[7];
    const float* ln2_g  = (const float*)d_in[8];
    const float* ln2_b  = (const float*)d_in[9];
    const float* fc1_w  = (const float*)d_in[10];
    const float* fc1_b  = (const float*)d_in[11];
    const float* fc2_w  = (const float*)d_in[12];
    const float* fc2_b  = (const float*)d_in[13];
    float* out = (float*)d_out;

    __nv_bfloat16 *p_ln1, *p_O, *p_ln2, *p_hid, *p_w;
    __half *p_qkv, *p_P;
    float *p_S, *p_x2;
    cudaGetSymbolAddress((void**)&p_ln1,  g_ln1b);
    cudaGetSymbolAddress((void**)&p_qkv,  g_qkvh);
    cudaGetSymbolAddress((void**)&p_S,    g_S);
    cudaGetSymbolAddress((void**)&p_P,    g_Ph);
    cudaGetSymbolAddress((void**)&p_O,    g_Ob);
    cudaGetSymbolAddress((void**)&p_x2,   g_x2);
    cudaGetSymbolAddress((void**)&p_ln2,  g_ln2b);
    cudaGetSymbolAddress((void**)&p_hid,  g_hidb);
    cudaGetSymbolAddress((void**)&p_w,    g_wall);

    // dynamic SMEM (bytes), 4 stages
    const int SM_NT96  = 4 * (128 * 40 + 96 * 40) * 2;    // 71680 (dense)
    const int SM_NT128 = 4 * (128 * 40 + 128 * 40) * 2;   // 81920 (QK fp16)
    const int SM_NN128 = 4 * (128 * 40 + 32 * 136) * 2;   // 75776 (PV fp16)
    cudaFuncSetAttribute(mma_gemm<128, 96, 1, 2>,
                         cudaFuncAttributeMaxDynamicSharedMemorySize, SM_NT96);
    cudaFuncSetAttribute(hmma_gemm<false, 0>,
                         cudaFuncAttributeMaxDynamicSharedMemorySize, SM_NT128);
    cudaFuncSetAttribute(hmma_gemm<true, 1>,
                         cudaFuncAttributeMaxDynamicSharedMemorySize, SM_NN128);
    cudaFuncSetAttribute(mma_gemm<128, 96, 3, 0>,
                         cudaFuncAttributeMaxDynamicSharedMemorySize, SM_NT96);
    cudaFuncSetAttribute(mma_gemm<128, 96, 2, 1>,
                         cudaFuncAttributeMaxDynamicSharedMemorySize, SM_NT96);

    f2bf_all<<<(W_TOT + 255)/256, 256>>>(qkv_w, proj_w, fc1_w, fc2_w, p_w);

    // 1. LN1
    ln_kernel<<<LT / 8, 256>>>(x, ln1_g, ln1_b, p_ln1);

    // 2. QKV -> fp16 [N, B_, 3C] flat
    mma_gemm<128, 96, 1, 2><<<dim3(3, LT / 128, 1), 256, SM_NT96>>>(
        p_ln1, CD, p_w + W_QKV, CD, qkv_b, nullptr, p_qkv, 3 * CD, CD, 1.0f);

    // 3. Logits: S[h] = scale * Q[h] @ K[h]^T  (fp16 acc)
    //    NOTE: ldc=NS (row stride), cZ=NS*NS (head stride)
    hmma_gemm<false, 0><<<dim3(NS / 128, NS / 128, NHD), 256, SM_NT128>>>(
        p_qkv, 3 * CD * 48, DA, p_qkv + 3 * DA, 3 * CD * 48, DA,
        p_S, NS, (long)NS * NS, DA, QK_SCALE);

    // 4. Softmax -> fp16 probs
    softmax_kernel<<<NHD * NS, 256>>>(p_S, p_P);

    // 5. O[h] = P[h] @ V[h] (NN, fp16 acc) -> bf16 g_O[n*4608 + h*1536 + d]
    //    NOTE: ldc=NHD*DA=4608 (row stride), cZ=DA=1536 (head offset)
    hmma_gemm<true, 1><<<dim3(DA / 128, NS / 128, NHD), 256, SM_NN128>>>(
        p_P, NS, (long)NS * NS, p_qkv + 6 * DA, 3 * CD * 48, DA,
        p_O, NHD * DA, DA, NS, 1.0f);

    // 6. proj + bias + residual(x) -> fp32 g_x2
    mma_gemm<128, 96, 3, 0><<<dim3(1, LT / 128, 1), 256, SM_NT96>>>(
        p_O, CD, p_w + W_PROJ, CD, proj_b, x, p_x2, CD, CD, 1.0f);

    // 7. LN2
    ln_kernel<<<LT / 8, 256>>>(p_x2, ln2_g, ln2_b, p_ln2);

    // 8. fc1 + bias + GELU
    mma_gemm<128, 96, 2, 1><<<dim3(HIDD / 96, LT / 128, 1), 256, SM_NT96>>>(
        p_ln2, CD, p_w + W_FC1, CD, fc1_b, nullptr, p_hid, HIDD, CD, 1.0f);

    // 9. fc2 + bias + residual
    mma_gemm<128, 96, 3, 0><<<dim3(1, LT / 128, 1), 256, SM_NT96>>>(
        p_hid, HIDD, p_w + W_FC2, HIDD, fc2_b, p_x2, out, CD, HIDD, 1.0f);
}

// round 14
// speedup vs baseline: 1.2682x; 1.0400x over previous
#include <cuda_runtime.h>
#include <cuda_bf16.h>
#include <cuda_fp16.h>
#include <math.h>
#include <stdint.h>

// Problem constants
#define LT   110592
#define CD   96
#define NS   2304
#define DA   1536
#define NHD  3
#define HIDD 384
#define QK_SCALE 0.17677669529663687f

// Scratch (device globals; alloc APIs banned)
__device__ __nv_bfloat16 g_ln1b[(size_t)LT * CD];
__device__ __half        g_qkvh[(size_t)LT * 3 * CD];   // fp16 qkv
__device__ float         g_S   [(size_t)NHD * NS * NS];
__device__ __half        g_Ph  [(size_t)NHD * NS * NS]; // fp16 probs
__device__ __nv_bfloat16 g_Ob  [(size_t)NS * NHD * DA];
__device__ float         g_x2  [(size_t)LT * CD];
__device__ __nv_bfloat16 g_ln2b[(size_t)LT * CD];
__device__ __nv_bfloat16 g_hidb[(size_t)LT * HIDD];
__device__ __nv_bfloat16 g_wall[110592];

#define W_QKV  0
#define W_PROJ (3 * CD * CD)
#define W_FC1  (W_PROJ + CD * CD)
#define W_FC2  (W_FC1 + HIDD * CD)
#define W_TOT  (W_FC2 + CD * HIDD)

// ---------------------------------------------------------------------------
__device__ __forceinline__ uint32_t s2u(const void* p) {
    return (uint32_t)__cvta_generic_to_shared(p);
}
__device__ __forceinline__ void ldsm4(uint32_t& r0, uint32_t& r1, uint32_t& r2, uint32_t& r3, uint32_t a) {
    asm volatile("ldmatrix.sync.aligned.m8n8.x4.shared.b16 {%0,%1,%2,%3}, [%4];\n"
                 : "=r"(r0), "=r"(r1), "=r"(r2), "=r"(r3) : "r"(a));
}
__device__ __forceinline__ void ldsm4t(uint32_t& r0, uint32_t& r1, uint32_t& r2, uint32_t& r3, uint32_t a) {
    asm volatile("ldmatrix.sync.aligned.m8n8.x4.trans.shared.b16 {%0,%1,%2,%3}, [%4];\n"
                 : "=r"(r0), "=r"(r1), "=r"(r2), "=r"(r3) : "r"(a));
}
__device__ __forceinline__ void mma16816(float* c, const uint32_t* a, const uint32_t* b) {
    asm volatile("mma.sync.aligned.m16n8k16.row.col.f32.bf16.bf16.f32 "
                 "{%0,%1,%2,%3}, {%4,%5,%6,%7}, {%8,%9}, {%0,%1,%2,%3};\n"
                 : "+f"(c[0]), "+f"(c[1]), "+f"(c[2]), "+f"(c[3])
                 : "r"(a[0]), "r"(a[1]), "r"(a[2]), "r"(a[3]), "r"(b[0]), "r"(b[1]));
}
__device__ __forceinline__ void mma16816h(uint32_t* c, const uint32_t* a, uint32_t b0, uint32_t b1) {
    asm volatile("mma.sync.aligned.m16n8k16.row.col.f16.f16.f16.f16 "
                 "{%0,%1}, {%2,%3,%4,%5}, {%6,%7}, {%0,%1};\n"
                 : "+r"(c[0]), "+r"(c[1])
                 : "r"(a[0]), "r"(a[1]), "r"(a[2]), "r"(a[3]), "r"(b0), "r"(b1));
}
__device__ __forceinline__ void cpa16(uint32_t dst, const void* src) {
    asm volatile("cp.async.cg.shared.global [%0], [%1], 16;\n" :: "r"(dst), "l"(src));
}
__device__ __forceinline__ void cpa_commit() {
    asm volatile("cp.async.commit_group;\n" ::: "memory");
}
__device__ __forceinline__ void cpa_wait1() {
    asm volatile("cp.async.wait_group 1;\n" ::: "memory");
}
__device__ __forceinline__ void cpa_wait2() {
    asm volatile("cp.async.wait_group 2;\n" ::: "memory");
}

// ---------------------------------------------------------------------------
__global__ void ln_kernel(const float* __restrict__ x, const float* __restrict__ g,
                          const float* __restrict__ b, __nv_bfloat16* __restrict__ out) {
    int wid  = (blockIdx.x * blockDim.x + threadIdx.x) >> 5;
    int lane = threadIdx.x & 31;
    if (wid >= LT) return;
    const float* row = x + (size_t)wid * CD;
    float v0 = row[lane], v1 = row[lane + 32], v2 = row[lane + 64];
    float s = v0 + v1 + v2;
    #pragma unroll
    for (int o = 16; o > 0; o >>= 1) s += __shfl_xor_sync(0xffffffffu, s, o);
    float mean = s * (1.0f / 96.0f);
    float d0 = v0 - mean, d1 = v1 - mean, d2 = v2 - mean;
    float vs = d0 * d0 + d1 * d1 + d2 * d2;
    #pragma unroll
    for (int o = 16; o > 0; o >>= 1) vs += __shfl_xor_sync(0xffffffffu, vs, o);
    float rstd = rsqrtf(vs * (1.0f / 96.0f) + 1e-5f);
    __nv_bfloat16* orow = out + (size_t)wid * CD;
    orow[lane]      = __float2bfloat16(d0 * rstd * g[lane]      + b[lane]);
    orow[lane + 32] = __float2bfloat16(d1 * rstd * g[lane + 32] + b[lane + 32]);
    orow[lane + 64] = __float2bfloat16(d2 * rstd * g[lane + 64] + b[lane + 64]);
}

__global__ void f2bf_all(const float* __restrict__ qkv, const float* __restrict__ proj,
                         const float* __restrict__ fc1, const float* __restrict__ fc2,
                         __nv_bfloat16* __restrict__ d) {
    int i = blockIdx.x * blockDim.x + threadIdx.x;
    if (i >= W_TOT) return;
    float v;
    if      (i < W_PROJ) v = qkv[i];
    else if (i < W_FC1)  v = proj[i - W_PROJ];
    else if (i < W_FC2)  v = fc1[i - W_FC1];
    else                 v = fc2[i - W_FC2];
    d[i] = __float2bfloat16(v);
}

// ---------------------------------------------------------------------------
__global__ void softmax_kernel(const float* __restrict__ S, __half* __restrict__ P) {
    const int row = blockIdx.x;
    const float* p = S + (size_t)row * NS;
    __half* q = P + (size_t)row * NS;
    const int tid = threadIdx.x;
    __shared__ float sm[8], ss[8];

    float v[9];
    float mx = -3.4e38f;
    #pragma unroll
    for (int i = 0; i < 9; i++) { v[i] = p[tid + 256 * i]; mx = fmaxf(mx, v[i]); }
    #pragma unroll
    for (int o = 16; o > 0; o >>= 1) mx = fmaxf(mx, __shfl_xor_sync(0xffffffffu, mx, o));
    if ((tid & 31) == 0) sm[tid >> 5] = mx;
    __syncthreads();
    mx = sm[0];
    #pragma unroll
    for (int i = 1; i < 8; i++) mx = fmaxf(mx, sm[i]);

    float sum = 0.0f;
    #pragma unroll
    for (int i = 0; i < 9; i++) { v[i] = __expf(v[i] - mx); sum += v[i]; }
    #pragma unroll
    for (int o = 16; o > 0; o >>= 1) sum += __shfl_xor_sync(0xffffffffu, sum, o);
    if ((tid & 31) == 0) ss[tid >> 5] = sum;
    __syncthreads();
    sum = 0.0f;
    #pragma unroll
    for (int i = 0; i < 8; i++) sum += ss[i];
    float inv = 1.0f / sum;
    #pragma unroll
    for (int i = 0; i < 9; i++) q[tid + 256 * i] = __float2half(v[i] * inv);
}

// ---------------------------------------------------------------------------
// bf16 warp-MMA GEMM (dense layers), 4-stage cp.async, 2 CTAs/SM. (unchanged, proven)
// ---------------------------------------------------------------------------
template<int BM, int BN, int EPI, int OUTM>
__global__ void __launch_bounds__(256, 2) mma_gemm(
    const __nv_bfloat16* __restrict__ A, int lda,
    const __nv_bfloat16* __restrict__ B, int ldb,
    const float* __restrict__ bias, const float* __restrict__ res,
    void* __restrict__ Cout, int ldc, int K, float alpha)
{
    constexpr int BK = 32, SA = BK + 8;
    constexpr int WM = 4, WN = 2;
    constexpr int WMT = BM / WM;
    constexpr int WNT = BN / WN;
    constexpr int MI = WMT / 16;
    constexpr int NI = WNT / 8;
    constexpr int THREADS = 256;
    constexpr int STAGE = BM * SA + BN * SA;
    constexpr int NSTG = 4;

    extern __shared__ __nv_bfloat16 smpb[];

    const int tid  = threadIdx.x;
    const int wid  = tid >> 5;
    const int lane = tid & 31;
    const int wm = wid / WN, wn = wid % WN;
    const int i0 = blockIdx.y * BM;
    const int n0 = blockIdx.x * BN;
    A += (size_t)i0 * lda;
    B += (size_t)n0 * ldb;

    float c[MI][NI][4];
    #pragma unroll
    for (int mi = 0; mi < MI; mi++)
        #pragma unroll
        for (int ni = 0; ni < NI; ni++)
            #pragma unroll
            for (int e = 0; e < 4; e++) c[mi][ni][e] = 0.0f;

    const int nKT = K / BK;

    auto load_stage = [&](int kt, int st) {
        __nv_bfloat16* As = smpb + st * STAGE;
        __nv_bfloat16* Bs = As + BM * SA;
        const __nv_bfloat16* Ag = A + kt * BK;
        #pragma unroll
        for (int e = tid; e < BM * 4; e += THREADS) {
            int m = e >> 2, kv = e & 3;
            cpa16(s2u(As + m * SA + kv * 8), Ag + (size_t)m * lda + kv * 8);
        }
        const __nv_bfloat16* Bg = B + kt * BK;
        #pragma unroll
        for (int e = tid; e < BN * 4; e += THREADS) {
            int n = e >> 2, kv = e & 3;
            cpa16(s2u(Bs + n * SA + kv * 8), Bg + (size_t)n * ldb + kv * 8);
        }
    };

    load_stage(0, 0); cpa_commit();
    if (nKT > 1) load_stage(1, 1);
    cpa_commit();
    if (nKT > 2) load_stage(2, 2);
    cpa_commit();

    for (int kt = 0; kt < nKT; kt++) {
        cpa_wait2();
        __syncthreads();
        if (kt + 3 < nKT) load_stage(kt + 3, (kt + 3) % NSTG);
        cpa_commit();

        const int st = kt % NSTG;
        __nv_bfloat16* As = smpb + st * STAGE;
        __nv_bfloat16* Bs = As + BM * SA;

        #pragma unroll
        for (int kk = 0; kk < 2; kk++) {
            uint32_t a[MI][4];
            #pragma unroll
            for (int mi = 0; mi < MI; mi++) {
                int m  = wm * WMT + mi * 16 + (lane & 15);
                int kc = kk * 16 + (lane >> 4) * 8;
                ldsm4(a[mi][0], a[mi][1], a[mi][2], a[mi][3], s2u(As + m * SA + kc));
            }
            uint32_t b[NI][2];
            #pragma unroll
            for (int np = 0; np < NI / 2; np++) {
                uint32_t r0, r1, r2, r3;
                int row = wn * WNT + np * 16 + (lane & 7) + ((lane >> 4) & 1) * 8;
                int col = kk * 16 + ((lane >> 3) & 1) * 8;
                ldsm4(r0, r1, r2, r3, s2u(Bs + row * SA + col));
                b[np * 2][0] = r0; b[np * 2][1] = r1;
                b[np * 2 + 1][0] = r2; b[np * 2 + 1][1] = r3;
            }
            #pragma unroll
            for (int mi = 0; mi < MI; mi++)
                #pragma unroll
                for (int ni = 0; ni < NI; ni++)
                    mma16816(c[mi][ni], a[mi], b[ni]);
        }
    }

    float* Cf = (float*)Cout;
    __nv_bfloat16* Cb = (__nv_bfloat16*)Cout;
    __half* Ch = (__half*)Cout;
    #pragma unroll
    for (int mi = 0; mi < MI; mi++) {
        int rbase = i0 + wm * WMT + mi * 16 + (lane >> 2);
        #pragma unroll
        for (int ni = 0; ni < NI; ni++) {
            int col = n0 + wn * WNT + ni * 8 + (lane & 3) * 2;
            #pragma unroll
            for (int hh = 0; hh < 2; hh++) {
                int r = rbase + hh * 8;
                float v0 = c[mi][ni][hh * 2 + 0] * alpha;
                float v1 = c[mi][ni][hh * 2 + 1] * alpha;
                if (EPI >= 1) { v0 += bias[col]; v1 += bias[col + 1]; }
                if (EPI == 2) {
                    v0 = 0.5f * v0 * (1.0f + erff(v0 * 0.70710678118654752f));
                    v1 = 0.5f * v1 * (1.0f + erff(v1 * 0.70710678118654752f));
                }
                if (EPI == 3) {
                    v0 += res[(size_t)r * ldc + col];
                    v1 += res[(size_t)r * ldc + col + 1];
                }
                if (OUTM == 0) {
                    float2 p; p.x = v0; p.y = v1;
                    *(float2*)&Cf[(size_t)r * ldc + col] = p;
                } else if (OUTM == 1) {
                    __nv_bfloat162 p;
                    p.x = __float2bfloat16(v0); p.y = __float2bfloat16(v1);
                    *(__nv_bfloat162*)&Cb[(size_t)r * ldc + col] = p;
                } else {
                    __half2 p = __floats2half2_rn(v0, v1);
                    *(__half2*)&Ch[(size_t)r * ldc + col] = p;
                }
            }
        }
    }
}

// ---------------------------------------------------------------------------
// fp16 warp-MMA GEMM (attention), fp16 acc, 3-stage cp.async, 3 CTAs/SM.
// Inner loop restructured: one B ldsm live at a time (register budget 84).
//   C = alpha * A @ op(B). BNN=false: B [N,K] (NT); BNN=true: B [K,N] (NN)
// OUTM: 0 fp32*alpha, 1 bf16
// ---------------------------------------------------------------------------
template<bool BNN, int OUTM>
__global__ void __launch_bounds__(256, 3) hmma_gemm(
    const __half* __restrict__ A, int lda, long aZ,
    const __half* __restrict__ B, int ldb, long bZ,
    void* __restrict__ Cout, int ldc, long cZ, int K, float alpha)
{
    constexpr int BM = 128, BN = 128;
    constexpr int BK = 32, SA = BK + 8;
    constexpr int WM = 4, WN = 2;
    constexpr int WMT = BM / WM;   // 32
    constexpr int WNT = BN / WN;   // 64
    constexpr int MI = 2, NI = 8;
    constexpr int THREADS = 256;
    constexpr int BSR = BNN ? BK : BN;
    constexpr int BSC = BNN ? BN + 8 : SA;
    constexpr int STAGE = BM * SA + BSR * BSC;
    constexpr int NSTG = 3;

    extern __shared__ __half smph[];

    const int tid  = threadIdx.x;
    const int wid  = tid >> 5;
    const int lane = tid & 31;
    const int wm = wid / WN, wn = wid % WN;
    const int i0 = blockIdx.y * BM;
    const int n0 = blockIdx.x * BN;
    A += (size_t)blockIdx.z * aZ + (size_t)i0 * lda;
    if (!BNN) B += (size_t)blockIdx.z * bZ + (size_t)n0 * ldb;
    else      B += (size_t)blockIdx.z * bZ + n0;

    uint32_t c[MI][NI][2];
    #pragma unroll
    for (int mi = 0; mi < MI; mi++)
        #pragma unroll
        for (int ni = 0; ni < NI; ni++) { c[mi][ni][0] = 0u; c[mi][ni][1] = 0u; }

    const int nKT = K / BK;

    auto load_stage = [&](int kt, int st) {
        __half* As = smph + st * STAGE;
        __half* Bs = As + BM * SA;
        const __half* Ag = A + kt * BK;
        #pragma unroll
        for (int e = tid; e < BM * 4; e += THREADS) {
            int m = e >> 2, kv = e & 3;
            cpa16(s2u(As + m * SA + kv * 8), Ag + (size_t)m * lda + kv * 8);
        }
        if (!BNN) {
            const __half* Bg = B + kt * BK;
            #pragma unroll
            for (int e = tid; e < BN * 4; e += THREADS) {
                int n = e >> 2, kv = e & 3;
                cpa16(s2u(Bs + n * SA + kv * 8), Bg + (size_t)n * ldb + kv * 8);
            }
        } else {
            const __half* Bg = B + (size_t)kt * BK * ldb;
            #pragma unroll
            for (int e = tid; e < BK * (BN / 8); e += THREADS) {
                int k = e / (BN / 8), nv = e % (BN / 8);
                cpa16(s2u(Bs + k * (BN + 8) + nv * 8), Bg + (size_t)k * ldb + nv * 8);
            }
        }
    };

    // prologue: 2 stages in flight
    load_stage(0, 0); cpa_commit();
    if (nKT > 1) load_stage(1, 1);
    cpa_commit();

    for (int kt = 0; kt < nKT; kt++) {
        cpa_wait1();
        __syncthreads();
        if (kt + 2 < nKT) load_stage(kt + 2, (kt + 2) % NSTG);
        cpa_commit();

        const int st = kt % NSTG;
        __half* As = smph + st * STAGE;
        __half* Bs = As + BM * SA;

        #pragma unroll
        for (int kk = 0; kk < 2; kk++) {
            uint32_t a[MI][4];
            #pragma unroll
            for (int mi = 0; mi < MI; mi++) {
                int m  = wm * WMT + mi * 16 + (lane & 15);
                int kc = kk * 16 + (lane >> 4) * 8;
                ldsm4(a[mi][0], a[mi][1], a[mi][2], a[mi][3], s2u(As + m * SA + kc));
            }
            // one B ldsm (2 n8 tiles) at a time -> 4 mma, keeps regs low
            #pragma unroll
            for (int np = 0; np < NI / 2; np++) {
                uint32_t r0, r1, r2, r3;
                if (!BNN) {
                    int row = wn * WNT + np * 16 + (lane & 7) + ((lane >> 4) & 1) * 8;
                    int col = kk * 16 + ((lane >> 3) & 1) * 8;
                    ldsm4(r0, r1, r2, r3, s2u(Bs + row * SA + col));
                } else {
                    int row = kk * 16 + (lane & 7) + ((lane >> 3) & 1) * 8;
                    int col = wn * WNT + np * 16 + ((lane >> 4) & 1) * 8;
                    ldsm4t(r0, r1, r2, r3, s2u(Bs + row * (BN + 8) + col));
                }
                mma16816h(c[0][np * 2],     a[0], r0, r1);
                mma16816h(c[1][np * 2],     a[1], r0, r1);
                mma16816h(c[0][np * 2 + 1], a[0], r2, r3);
                mma16816h(c[1][np * 2 + 1], a[1], r2, r3);
            }
        }
    }

    // Epilogue
    float* Cf = (float*)Cout + (size_t)blockIdx.z * cZ;
    __nv_bfloat16* Cb = (__nv_bfloat16*)Cout + (size_t)blockIdx.z * cZ;
    #pragma unroll
    for (int mi = 0; mi < MI; mi++) {
        int rbase = i0 + wm * WMT + mi * 16 + (lane >> 2);
        #pragma unroll
        for (int ni = 0; ni < NI; ni++) {
            int col = n0 + wn * WNT + ni * 8 + (lane & 3) * 2;
            #pragma unroll
            for (int hh = 0; hh < 2; hh++) {
                int r = rbase + hh * 8;
                __half2 hv = *(__half2*)&c[mi][ni][hh];
                float2 f = __half22float2(hv);
                if (OUTM == 0) {
                    float2 p; p.x = f.x * alpha; p.y = f.y * alpha;
                    *(float2*)&Cf[(size_t)r * ldc + col] = p;
                } else {
                    __nv_bfloat162 p;
                    p.x = __float2bfloat16(f.x); p.y = __float2bfloat16(f.y);
                    *(__nv_bfloat162*)&Cb[(size_t)r * ldc + col] = p;
                }
            }
        }
    }
}

// ---------------------------------------------------------------------------
extern "C" void kernel_launch(void* const* d_in, const int* in_sizes, int n_in,
                              void* d_out, int out_size) {
    const float* x      = (const float*)d_in[0];
    const float* ln1_g  = (const float*)d_in[2];
    const float* ln1_b  = (const float*)d_in[3];
    const float* qkv_w  = (const float*)d_in[4];
    const float* qkv_b  = (const float*)d_in[5];
    const float* proj_w = (const float*)d_in[6];
    const float* proj_b = (const float*)d_in[7];
    const float* ln2_g  = (const float*)d_in[8];
    const float* ln2_b  = (const float*)d_in[9];
    const float* fc1_w  = (const float*)d_in[10];
    const float* fc1_b  = (const float*)d_in[11];
    const float* fc2_w  = (const float*)d_in[12];
    const float* fc2_b  = (const float*)d_in[13];
    float* out = (float*)d_out;

    __nv_bfloat16 *p_ln1, *p_O, *p_ln2, *p_hid, *p_w;
    __half *p_qkv, *p_P;
    float *p_S, *p_x2;
    cudaGetSymbolAddress((void**)&p_ln1,  g_ln1b);
    cudaGetSymbolAddress((void**)&p_qkv,  g_qkvh);
    cudaGetSymbolAddress((void**)&p_S,    g_S);
    cudaGetSymbolAddress((void**)&p_P,    g_Ph);
    cudaGetSymbolAddress((void**)&p_O,    g_Ob);
    cudaGetSymbolAddress((void**)&p_x2,   g_x2);
    cudaGetSymbolAddress((void**)&p_ln2,  g_ln2b);
    cudaGetSymbolAddress((void**)&p_hid,  g_hidb);
    cudaGetSymbolAddress((void**)&p_w,    g_wall);

    // dynamic SMEM (bytes)
    const int SM_NT96  = 4 * (128 * 40 + 96 * 40) * 2;    // 71680 (dense, 4-stage)
    const int SM_NT128 = 3 * (128 * 40 + 128 * 40) * 2;   // 61440 (QK fp16, 3-stage)
    const int SM_NN128 = 3 * (128 * 40 + 32 * 136) * 2;   // 56832 (PV fp16, 3-stage)
    cudaFuncSetAttribute(mma_gemm<128, 96, 1, 2>,
                         cudaFuncAttributeMaxDynamicSharedMemorySize, SM_NT96);
    cudaFuncSetAttribute(hmma_gemm<false, 0>,
                         cudaFuncAttributeMaxDynamicSharedMemorySize, SM_NT128);
    cudaFuncSetAttribute(hmma_gemm<true, 1>,
                         cudaFuncAttributeMaxDynamicSharedMemorySize, SM_NN128);
    cudaFuncSetAttribute(mma_gemm<128, 96, 3, 0>,
                         cudaFuncAttributeMaxDynamicSharedMemorySize, SM_NT96);
    cudaFuncSetAttribute(mma_gemm<128, 96, 2, 1>,
                         cudaFuncAttributeMaxDynamicSharedMemorySize, SM_NT96);

    f2bf_all<<<(W_TOT + 255)/256, 256>>>(qkv_w, proj_w, fc1_w, fc2_w, p_w);

    // 1. LN1
    ln_kernel<<<LT / 8, 256>>>(x, ln1_g, ln1_b, p_ln1);

    // 2. QKV -> fp16 [N, B_, 3C] flat
    mma_gemm<128, 96, 1, 2><<<dim3(3, LT / 128, 1), 256, SM_NT96>>>(
        p_ln1, CD, p_w + W_QKV, CD, qkv_b, nullptr, p_qkv, 3 * CD, CD, 1.0f);

    // 3. Logits: S[h] = scale * Q[h] @ K[h]^T  (fp16 acc, 3 CTAs/SM)
    hmma_gemm<false, 0><<<dim3(NS / 128, NS / 128, NHD), 256, SM_NT128>>>(
        p_qkv, 3 * CD * 48, DA, p_qkv + 3 * DA, 3 * CD * 48, DA,
        p_S, NS, (long)NS * NS, DA, QK_SCALE);

    // 4. Softmax -> fp16 probs
    softmax_kernel<<<NHD * NS, 256>>>(p_S, p_P);

    // 5. O[h] = P[h] @ V[h] (NN, fp16 acc) -> bf16 g_O[n*4608 + h*1536 + d]
    hmma_gemm<true, 1><<<dim3(DA / 128, NS / 128, NHD), 256, SM_NN128>>>(
        p_P, NS, (long)NS * NS, p_qkv + 6 * DA, 3 * CD * 48, DA,
        p_O, NHD * DA, DA, NS, 1.0f);

    // 6. proj + bias + residual(x) -> fp32 g_x2
    mma_gemm<128, 96, 3, 0><<<dim3(1, LT / 128, 1), 256, SM_NT96>>>(
        p_O, CD, p_w + W_PROJ, CD, proj_b, x, p_x2, CD, CD, 1.0f);

    // 7. LN2
    ln_kernel<<<LT / 8, 256>>>(p_x2, ln2_g, ln2_b, p_ln2);

    // 8. fc1 + bias + GELU
    mma_gemm<128, 96, 2, 1><<<dim3(HIDD / 96, LT / 128, 1), 256, SM_NT96>>>(
        p_ln2, CD, p_w + W_FC1, CD, fc1_b, nullptr, p_hid, HIDD, CD, 1.0f);

    // 9. fc2 + bias + residual
    mma_gemm<128, 96, 3, 0><<<dim3(1, LT / 128, 1), 256, SM_NT96>>>(
        p_hid, HIDD, p_w + W_FC2, HIDD, fc2_b, p_x2, out, CD, HIDD, 1.0f);
}

// round 15
// speedup vs baseline: 1.2711x; 1.0023x over previous
#include <cuda_runtime.h>
#include <cuda_bf16.h>
#include <cuda_fp16.h>
#include <math.h>
#include <stdint.h>

// Problem constants
#define LT   110592
#define CD   96
#define NS   2304
#define DA   1536
#define NHD  3
#define HIDD 384
#define QK_SCALE 0.17677669529663687f

// Scratch (device globals; alloc APIs banned)
__device__ __nv_bfloat16 g_ln1b[(size_t)LT * CD];
__device__ __half        g_qkvh[(size_t)LT * 3 * CD];   // fp16 qkv
__device__ __half        g_Sh  [(size_t)NHD * NS * NS]; // fp16 logits
__device__ __half        g_Ph  [(size_t)NHD * NS * NS]; // fp16 probs
__device__ __nv_bfloat16 g_Ob  [(size_t)NS * NHD * DA];
__device__ float         g_x2  [(size_t)LT * CD];
__device__ __nv_bfloat16 g_ln2b[(size_t)LT * CD];
__device__ __nv_bfloat16 g_hidb[(size_t)LT * HIDD];
__device__ __nv_bfloat16 g_wall[110592];

#define W_QKV  0
#define W_PROJ (3 * CD * CD)
#define W_FC1  (W_PROJ + CD * CD)
#define W_FC2  (W_FC1 + HIDD * CD)
#define W_TOT  (W_FC2 + CD * HIDD)

// ---------------------------------------------------------------------------
__device__ __forceinline__ uint32_t s2u(const void* p) {
    return (uint32_t)__cvta_generic_to_shared(p);
}
__device__ __forceinline__ void ldsm4(uint32_t& r0, uint32_t& r1, uint32_t& r2, uint32_t& r3, uint32_t a) {
    asm volatile("ldmatrix.sync.aligned.m8n8.x4.shared.b16 {%0,%1,%2,%3}, [%4];\n"
                 : "=r"(r0), "=r"(r1), "=r"(r2), "=r"(r3) : "r"(a));
}
__device__ __forceinline__ void ldsm4t(uint32_t& r0, uint32_t& r1, uint32_t& r2, uint32_t& r3, uint32_t a) {
    asm volatile("ldmatrix.sync.aligned.m8n8.x4.trans.shared.b16 {%0,%1,%2,%3}, [%4];\n"
                 : "=r"(r0), "=r"(r1), "=r"(r2), "=r"(r3) : "r"(a));
}
__device__ __forceinline__ void mma16816(float* c, const uint32_t* a, const uint32_t* b) {
    asm volatile("mma.sync.aligned.m16n8k16.row.col.f32.bf16.bf16.f32 "
                 "{%0,%1,%2,%3}, {%4,%5,%6,%7}, {%8,%9}, {%0,%1,%2,%3};\n"
                 : "+f"(c[0]), "+f"(c[1]), "+f"(c[2]), "+f"(c[3])
                 : "r"(a[0]), "r"(a[1]), "r"(a[2]), "r"(a[3]), "r"(b[0]), "r"(b[1]));
}
__device__ __forceinline__ void mma16816h(uint32_t* c, const uint32_t* a, uint32_t b0, uint32_t b1) {
    asm volatile("mma.sync.aligned.m16n8k16.row.col.f16.f16.f16.f16 "
                 "{%0,%1}, {%2,%3,%4,%5}, {%6,%7}, {%0,%1};\n"
                 : "+r"(c[0]), "+r"(c[1])
                 : "r"(a[0]), "r"(a[1]), "r"(a[2]), "r"(a[3]), "r"(b0), "r"(b1));
}
__device__ __forceinline__ void cpa16(uint32_t dst, const void* src) {
    asm volatile("cp.async.cg.shared.global [%0], [%1], 16;\n" :: "r"(dst), "l"(src));
}
__device__ __forceinline__ void cpa_commit() {
    asm volatile("cp.async.commit_group;\n" ::: "memory");
}
__device__ __forceinline__ void cpa_wait1() {
    asm volatile("cp.async.wait_group 1;\n" ::: "memory");
}
__device__ __forceinline__ void cpa_wait2() {
    asm volatile("cp.async.wait_group 2;\n" ::: "memory");
}

// ---------------------------------------------------------------------------
__global__ void ln_kernel(const float* __restrict__ x, const float* __restrict__ g,
                          const float* __restrict__ b, __nv_bfloat16* __restrict__ out) {
    int wid  = (blockIdx.x * blockDim.x + threadIdx.x) >> 5;
    int lane = threadIdx.x & 31;
    if (wid >= LT) return;
    const float* row = x + (size_t)wid * CD;
    float v0 = row[lane], v1 = row[lane + 32], v2 = row[lane + 64];
    float s = v0 + v1 + v2;
    #pragma unroll
    for (int o = 16; o > 0; o >>= 1) s += __shfl_xor_sync(0xffffffffu, s, o);
    float mean = s * (1.0f / 96.0f);
    float d0 = v0 - mean, d1 = v1 - mean, d2 = v2 - mean;
    float vs = d0 * d0 + d1 * d1 + d2 * d2;
    #pragma unroll
    for (int o = 16; o > 0; o >>= 1) vs += __shfl_xor_sync(0xffffffffu, vs, o);
    float rstd = rsqrtf(vs * (1.0f / 96.0f) + 1e-5f);
    __nv_bfloat16* orow = out + (size_t)wid * CD;
    orow[lane]      = __float2bfloat16(d0 * rstd * g[lane]      + b[lane]);
    orow[lane + 32] = __float2bfloat16(d1 * rstd * g[lane + 32] + b[lane + 32]);
    orow[lane + 64] = __float2bfloat16(d2 * rstd * g[lane + 64] + b[lane + 64]);
}

__global__ void f2bf_all(const float* __restrict__ qkv, const float* __restrict__ proj,
                         const float* __restrict__ fc1, const float* __restrict__ fc2,
                         __nv_bfloat16* __restrict__ d) {
    int i = blockIdx.x * blockDim.x + threadIdx.x;
    if (i >= W_TOT) return;
    float v;
    if      (i < W_PROJ) v = qkv[i];
    else if (i < W_FC1)  v = proj[i - W_PROJ];
    else if (i < W_FC2)  v = fc1[i - W_FC1];
    else                 v = fc2[i - W_FC2];
    d[i] = __float2bfloat16(v);
}

// ---------------------------------------------------------------------------
// Row softmax over 2304 cols (fp16 in, fp16 out)
// ---------------------------------------------------------------------------
__global__ void softmax_kernel(const __half* __restrict__ S, __half* __restrict__ P) {
    const int row = blockIdx.x;
    const __half* p = S + (size_t)row * NS;
    __half* q = P + (size_t)row * NS;
    const int tid = threadIdx.x;
    __shared__ float sm[8], ss[8];

    float v[9];
    float mx = -3.4e38f;
    #pragma unroll
    for (int i = 0; i < 9; i++) { v[i] = __half2float(p[tid + 256 * i]); mx = fmaxf(mx, v[i]); }
    #pragma unroll
    for (int o = 16; o > 0; o >>= 1) mx = fmaxf(mx, __shfl_xor_sync(0xffffffffu, mx, o));
    if ((tid & 31) == 0) sm[tid >> 5] = mx;
    __syncthreads();
    mx = sm[0];
    #pragma unroll
    for (int i = 1; i < 8; i++) mx = fmaxf(mx, sm[i]);

    float sum = 0.0f;
    #pragma unroll
    for (int i = 0; i < 9; i++) { v[i] = __expf(v[i] - mx); sum += v[i]; }
    #pragma unroll
    for (int o = 16; o > 0; o >>= 1) sum += __shfl_xor_sync(0xffffffffu, sum, o);
    if ((tid & 31) == 0) ss[tid >> 5] = sum;
    __syncthreads();
    sum = 0.0f;
    #pragma unroll
    for (int i = 0; i < 8; i++) sum += ss[i];
    float inv = 1.0f / sum;
    #pragma unroll
    for (int i = 0; i < 9; i++) q[tid + 256 * i] = __float2half(v[i] * inv);
}

// ---------------------------------------------------------------------------
// bf16 warp-MMA GEMM (dense layers), 4-stage cp.async, 2 CTAs/SM.
// C = alpha*A@B^T (+epi). OUTM: 0 fp32, 1 bf16, 2 fp16
// EPI: 0 none, 1 +bias, 2 +bias+gelu, 3 +bias+residual,
//      4 +bias+residual -> Cout(fp32)  AND fused LayerNorm -> Cout2(bf16)
// ---------------------------------------------------------------------------
template<int BM, int BN, int EPI, int OUTM>
__global__ void __launch_bounds__(256, 2) mma_gemm(
    const __nv_bfloat16* __restrict__ A, int lda,
    const __nv_bfloat16* __restrict__ B, int ldb,
    const float* __restrict__ bias, const float* __restrict__ res,
    void* __restrict__ Cout, int ldc, int K, float alpha,
    const float* __restrict__ g2, const float* __restrict__ b2,
    void* __restrict__ Cout2)
{
    constexpr int BK = 32, SA = BK + 8;
    constexpr int WM = 4, WN = 2;
    constexpr int WMT = BM / WM;
    constexpr int WNT = BN / WN;
    constexpr int MI = WMT / 16;
    constexpr int NI = WNT / 8;
    constexpr int THREADS = 256;
    constexpr int STAGE = BM * SA + BN * SA;
    constexpr int NSTG = 4;

    extern __shared__ __nv_bfloat16 smpb[];
    __shared__ float red[EPI == 4 ? 2 : 1][EPI == 4 ? BM : 1][8];

    const int tid  = threadIdx.x;
    const int wid  = tid >> 5;
    const int lane = tid & 31;
    const int wm = wid / WN, wn = wid % WN;
    const int i0 = blockIdx.y * BM;
    const int n0 = blockIdx.x * BN;
    A += (size_t)i0 * lda;
    B += (size_t)n0 * ldb;

    float c[MI][NI][4];
    #pragma unroll
    for (int mi = 0; mi < MI; mi++)
        #pragma unroll
        for (int ni = 0; ni < NI; ni++)
            #pragma unroll
            for (int e = 0; e < 4; e++) c[mi][ni][e] = 0.0f;

    const int nKT = K / BK;

    auto load_stage = [&](int kt, int st) {
        __nv_bfloat16* As = smpb + st * STAGE;
        __nv_bfloat16* Bs = As + BM * SA;
        const __nv_bfloat16* Ag = A + kt * BK;
        #pragma unroll
        for (int e = tid; e < BM * 4; e += THREADS) {
            int m = e >> 2, kv = e & 3;
            cpa16(s2u(As + m * SA + kv * 8), Ag + (size_t)m * lda + kv * 8);
        }
        const __nv_bfloat16* Bg = B + kt * BK;
        #pragma unroll
        for (int e = tid; e < BN * 4; e += THREADS) {
            int n = e >> 2, kv = e & 3;
            cpa16(s2u(Bs + n * SA + kv * 8), Bg + (size_t)n * ldb + kv * 8);
        }
    };

    load_stage(0, 0); cpa_commit();
    if (nKT > 1) load_stage(1, 1);
    cpa_commit();
    if (nKT > 2) load_stage(2, 2);
    cpa_commit();

    for (int kt = 0; kt < nKT; kt++) {
        cpa_wait2();
        __syncthreads();
        if (kt + 3 < nKT) load_stage(kt + 3, (kt + 3) % NSTG);
        cpa_commit();

        const int st = kt % NSTG;
        __nv_bfloat16* As = smpb + st * STAGE;
        __nv_bfloat16* Bs = As + BM * SA;

        #pragma unroll
        for (int kk = 0; kk < 2; kk++) {
            uint32_t a[MI][4];
            #pragma unroll
            for (int mi = 0; mi < MI; mi++) {
                int m  = wm * WMT + mi * 16 + (lane & 15);
                int kc = kk * 16 + (lane >> 4) * 8;
                ldsm4(a[mi][0], a[mi][1], a[mi][2], a[mi][3], s2u(As + m * SA + kc));
            }
            uint32_t b[NI][2];
            #pragma unroll
            for (int np = 0; np < NI / 2; np++) {
                uint32_t r0, r1, r2, r3;
                int row = wn * WNT + np * 16 + (lane & 7) + ((lane >> 4) & 1) * 8;
                int col = kk * 16 + ((lane >> 3) & 1) * 8;
                ldsm4(r0, r1, r2, r3, s2u(Bs + row * SA + col));
                b[np * 2][0] = r0; b[np * 2][1] = r1;
                b[np * 2 + 1][0] = r2; b[np * 2 + 1][1] = r3;
            }
            #pragma unroll
            for (int mi = 0; mi < MI; mi++)
                #pragma unroll
                for (int ni = 0; ni < NI; ni++)
                    mma16816(c[mi][ni], a[mi], b[ni]);
        }
    }

    if (EPI == 4) {
        // ---- fused bias + residual + x2 store + LayerNorm store ----
        float psum[MI][2], psq[MI][2];
        #pragma unroll
        for (int mi = 0; mi < MI; mi++)
            #pragma unroll
            for (int hh = 0; hh < 2; hh++) { psum[mi][hh] = 0.0f; psq[mi][hh] = 0.0f; }

        #pragma unroll
        for (int mi = 0; mi < MI; mi++) {
            #pragma unroll
            for (int ni = 0; ni < NI; ni++) {
                int col = n0 + wn * WNT + ni * 8 + (lane & 3) * 2;
                #pragma unroll
                for (int hh = 0; hh < 2; hh++) {
                    int r = i0 + wm * WMT + mi * 16 + (lane >> 2) + hh * 8;
                    float v0 = c[mi][ni][hh * 2 + 0] + bias[col]     + res[(size_t)r * ldc + col];
                    float v1 = c[mi][ni][hh * 2 + 1] + bias[col + 1] + res[(size_t)r * ldc + col + 1];
                    c[mi][ni][hh * 2 + 0] = v0;
                    c[mi][ni][hh * 2 + 1] = v1;
                    psum[mi][hh] += v0 + v1;
                    psq[mi][hh]  += v0 * v0 + v1 * v1;
                }
            }
        }
        int slot = wn * 4 + (lane & 3);
        #pragma unroll
        for (int mi = 0; mi < MI; mi++)
            #pragma unroll
            for (int hh = 0; hh < 2; hh++) {
                int lr = wm * WMT + mi * 16 + (lane >> 2) + hh * 8;
                red[0][lr][slot] = psum[mi][hh];
                red[1][lr][slot] = psq[mi][hh];
            }
        __syncthreads();

        float mus[MI][2], rstds[MI][2];
        #pragma unroll
        for (int mi = 0; mi < MI; mi++)
            #pragma unroll
            for (int hh = 0; hh < 2; hh++) {
                int lr = wm * WMT + mi * 16 + (lane >> 2) + hh * 8;
                float s = 0.0f, q = 0.0f;
                #pragma unroll
                for (int k = 0; k < 8; k++) { s += red[0][lr][k]; q += red[1][lr][k]; }
                float mu = s * (1.0f / 96.0f);
                mus[mi][hh] = mu;
                rstds[mi][hh] = rsqrtf(q * (1.0f / 96.0f) - mu * mu + 1e-5f);
            }

        float* X2 = (float*)Cout;
        __nv_bfloat16* L2 = (__nv_bfloat16*)Cout2;
        #pragma unroll
        for (int mi = 0; mi < MI; mi++) {
            #pragma unroll
            for (int ni = 0; ni < NI; ni++) {
                int col = n0 + wn * WNT + ni * 8 + (lane & 3) * 2;
                float gg0 = g2[col], gg1 = g2[col + 1];
                float bb0 = b2[col], bb1 = b2[col + 1];
                #pragma unroll
                for (int hh = 0; hh < 2; hh++) {
                    int r = i0 + wm * WMT + mi * 16 + (lane >> 2) + hh * 8;
                    float v0 = c[mi][ni][hh * 2 + 0];
                    float v1 = c[mi][ni][hh * 2 + 1];
                    float2 p; p.x = v0; p.y = v1;
                    *(float2*)&X2[(size_t)r * ldc + col] = p;
                    float mu = mus[mi][hh], rs = rstds[mi][hh];
                    __nv_bfloat162 lp;
                    lp.x = __float2bfloat16((v0 - mu) * rs * gg0 + bb0);
                    lp.y = __float2bfloat16((v1 - mu) * rs * gg1 + bb1);
                    *(__nv_bfloat162*)&L2[(size_t)r * ldc + col] = lp;
                }
            }
        }
        return;
    }

    float* Cf = (float*)Cout;
    __nv_bfloat16* Cb = (__nv_bfloat16*)Cout;
    __half* Ch = (__half*)Cout;
    #pragma unroll
    for (int mi = 0; mi < MI; mi++) {
        int rbase = i0 + wm * WMT + mi * 16 + (lane >> 2);
        #pragma unroll
        for (int ni = 0; ni < NI; ni++) {
            int col = n0 + wn * WNT + ni * 8 + (lane & 3) * 2;
            #pragma unroll
            for (int hh = 0; hh < 2; hh++) {
                int r = rbase + hh * 8;
                float v0 = c[mi][ni][hh * 2 + 0] * alpha;
                float v1 = c[mi][ni][hh * 2 + 1] * alpha;
                if (EPI >= 1) { v0 += bias[col]; v1 += bias[col + 1]; }
                if (EPI == 2) {
                    v0 = 0.5f * v0 * (1.0f + erff(v0 * 0.70710678118654752f));
                    v1 = 0.5f * v1 * (1.0f + erff(v1 * 0.70710678118654752f));
                }
                if (EPI == 3) {
                    v0 += res[(size_t)r * ldc + col];
                    v1 += res[(size_t)r * ldc + col + 1];
                }
                if (OUTM == 0) {
                    float2 p; p.x = v0; p.y = v1;
                    *(float2*)&Cf[(size_t)r * ldc + col] = p;
                } else if (OUTM == 1) {
                    __nv_bfloat162 p;
                    p.x = __float2bfloat16(v0); p.y = __float2bfloat16(v1);
                    *(__nv_bfloat162*)&Cb[(size_t)r * ldc + col] = p;
                } else {
                    __half2 p = __floats2half2_rn(v0, v1);
                    *(__half2*)&Ch[(size_t)r * ldc + col] = p;
                }
            }
        }
    }
}

// ---------------------------------------------------------------------------
// fp16 warp-MMA GEMM (attention), fp16 acc, 3-stage cp.async, 3 CTAs/SM.
//   C = alpha * A @ op(B). BNN=false: B [N,K] (NT); BNN=true: B [K,N] (NN)
// OUTM: 0 fp32*alpha, 1 bf16, 2 fp16*alpha
// ---------------------------------------------------------------------------
template<bool BNN, int OUTM>
__global__ void __launch_bounds__(256, 3) hmma_gemm(
    const __half* __restrict__ A, int lda, long aZ,
    const __half* __restrict__ B, int ldb, long bZ,
    void* __restrict__ Cout, int ldc, long cZ, int K, float alpha)
{
    constexpr int BM = 128, BN = 128;
    constexpr int BK = 32, SA = BK + 8;
    constexpr int WM = 4, WN = 2;
    constexpr int WMT = BM / WM;   // 32
    constexpr int WNT = BN / WN;   // 64
    constexpr int MI = 2, NI = 8;
    constexpr int THREADS = 256;
    constexpr int BSR = BNN ? BK : BN;
    constexpr int BSC = BNN ? BN + 8 : SA;
    constexpr int STAGE = BM * SA + BSR * BSC;
    constexpr int NSTG = 3;

    extern __shared__ __half smph[];

    const int tid  = threadIdx.x;
    const int wid  = tid >> 5;
    const int lane = tid & 31;
    const int wm = wid / WN, wn = wid % WN;
    const int i0 = blockIdx.y * BM;
    const int n0 = blockIdx.x * BN;
    A += (size_t)blockIdx.z * aZ + (size_t)i0 * lda;
    if (!BNN) B += (size_t)blockIdx.z * bZ + (size_t)n0 * ldb;
    else      B += (size_t)blockIdx.z * bZ + n0;

    uint32_t c[MI][NI][2];
    #pragma unroll
    for (int mi = 0; mi < MI; mi++)
        #pragma unroll
        for (int ni = 0; ni < NI; ni++) { c[mi][ni][0] = 0u; c[mi][ni][1] = 0u; }

    const int nKT = K / BK;

    auto load_stage = [&](int kt, int st) {
        __half* As = smph + st * STAGE;
        __half* Bs = As + BM * SA;
        const __half* Ag = A + kt * BK;
        #pragma unroll
        for (int e = tid; e < BM * 4; e += THREADS) {
            int m = e >> 2, kv = e & 3;
            cpa16(s2u(As + m * SA + kv * 8), Ag + (size_t)m * lda + kv * 8);
        }
        if (!BNN) {
            const __half* Bg = B + kt * BK;
            #pragma unroll
            for (int e = tid; e < BN * 4; e += THREADS) {
                int n = e >> 2, kv = e & 3;
                cpa16(s2u(Bs + n * SA + kv * 8), Bg + (size_t)n * ldb + kv * 8);
            }
        } else {
            const __half* Bg = B + (size_t)kt * BK * ldb;
            #pragma unroll
            for (int e = tid; e < BK * (BN / 8); e += THREADS) {
                int k = e / (BN / 8), nv = e % (BN / 8);
                cpa16(s2u(Bs + k * (BN + 8) + nv * 8), Bg + (size_t)k * ldb + nv * 8);
            }
        }
    };

    // prologue: 2 stages in flight
    load_stage(0, 0); cpa_commit();
    if (nKT > 1) load_stage(1, 1);
    cpa_commit();

    for (int kt = 0; kt < nKT; kt++) {
        cpa_wait1();
        __syncthreads();
        if (kt + 2 < nKT) load_stage(kt + 2, (kt + 2) % NSTG);
        cpa_commit();

        const int st = kt % NSTG;
        __half* As = smph + st * STAGE;
        __half* Bs = As + BM * SA;

        #pragma unroll
        for (int kk = 0; kk < 2; kk++) {
            uint32_t a[MI][4];
            #pragma unroll
            for (int mi = 0; mi < MI; mi++) {
                int m  = wm * WMT + mi * 16 + (lane & 15);
                int kc = kk * 16 + (lane >> 4) * 8;
                ldsm4(a[mi][0], a[mi][1], a[mi][2], a[mi][3], s2u(As + m * SA + kc));
            }
            #pragma unroll
            for (int np = 0; np < NI / 2; np++) {
                uint32_t r0, r1, r2, r3;
                if (!BNN) {
                    int row = wn * WNT + np * 16 + (lane & 7) + ((lane >> 4) & 1) * 8;
                    int col = kk * 16 + ((lane >> 3) & 1) * 8;
                    ldsm4(r0, r1, r2, r3, s2u(Bs + row * SA + col));
                } else {
                    int row = kk * 16 + (lane & 7) + ((lane >> 3) & 1) * 8;
                    int col = wn * WNT + np * 16 + ((lane >> 4) & 1) * 8;
                    ldsm4t(r0, r1, r2, r3, s2u(Bs + row * (BN + 8) + col));
                }
                mma16816h(c[0][np * 2],     a[0], r0, r1);
                mma16816h(c[1][np * 2],     a[1], r0, r1);
                mma16816h(c[0][np * 2 + 1], a[0], r2, r3);
                mma16816h(c[1][np * 2 + 1], a[1], r2, r3);
            }
        }
    }

    // Epilogue
    float* Cf = (float*)Cout + (size_t)blockIdx.z * cZ;
    __nv_bfloat16* Cb = (__nv_bfloat16*)Cout + (size_t)blockIdx.z * cZ;
    __half* Chh = (__half*)Cout + (size_t)blockIdx.z * cZ;
    #pragma unroll
    for (int mi = 0; mi < MI; mi++) {
        int rbase = i0 + wm * WMT + mi * 16 + (lane >> 2);
        #pragma unroll
        for (int ni = 0; ni < NI; ni++) {
            int col = n0 + wn * WNT + ni * 8 + (lane & 3) * 2;
            #pragma unroll
            for (int hh = 0; hh < 2; hh++) {
                int r = rbase + hh * 8;
                __half2 hv = *(__half2*)&c[mi][ni][hh];
                float2 f = __half22float2(hv);
                if (OUTM == 0) {
                    float2 p; p.x = f.x * alpha; p.y = f.y * alpha;
                    *(float2*)&Cf[(size_t)r * ldc + col] = p;
                } else if (OUTM == 1) {
                    __nv_bfloat162 p;
                    p.x = __float2bfloat16(f.x); p.y = __float2bfloat16(f.y);
                    *(__nv_bfloat162*)&Cb[(size_t)r * ldc + col] = p;
                } else {
                    __half2 p = __floats2half2_rn(f.x * alpha, f.y * alpha);
                    *(__half2*)&Chh[(size_t)r * ldc + col] = p;
                }
            }
        }
    }
}

// ---------------------------------------------------------------------------
extern "C" void kernel_launch(void* const* d_in, const int* in_sizes, int n_in,
                              void* d_out, int out_size) {
    const float* x      = (const float*)d_in[0];
    const float* ln1_g  = (const float*)d_in[2];
    const float* ln1_b  = (const float*)d_in[3];
    const float* qkv_w  = (const float*)d_in[4];
    const float* qkv_b  = (const float*)d_in[5];
    const float* proj_w = (const float*)d_in[6];
    const float* proj_b = (const float*)d_in[7];
    const float* ln2_g  = (const float*)d_in[8];
    const float* ln2_b  = (const float*)d_in[9];
    const float* fc1_w  = (const float*)d_in[10];
    const float* fc1_b  = (const float*)d_in[11];
    const float* fc2_w  = (const float*)d_in[12];
    const float* fc2_b  = (const float*)d_in[13];
    float* out = (float*)d_out;

    __nv_bfloat16 *p_ln1, *p_O, *p_ln2, *p_hid, *p_w;
    __half *p_qkv, *p_S, *p_P;
    float *p_x2;
    cudaGetSymbolAddress((void**)&p_ln1,  g_ln1b);
    cudaGetSymbolAddress((void**)&p_qkv,  g_qkvh);
    cudaGetSymbolAddress((void**)&p_S,    g_Sh);
    cudaGetSymbolAddress((void**)&p_P,    g_Ph);
    cudaGetSymbolAddress((void**)&p_O,    g_Ob);
    cudaGetSymbolAddress((void**)&p_x2,   g_x2);
    cudaGetSymbolAddress((void**)&p_ln2,  g_ln2b);
    cudaGetSymbolAddress((void**)&p_hid,  g_hidb);
    cudaGetSymbolAddress((void**)&p_w,    g_wall);

    // dynamic SMEM (bytes)
    const int SM_NT96  = 4 * (128 * 40 + 96 * 40) * 2;    // 71680 (dense, 4-stage)
    const int SM_NT128 = 3 * (128 * 40 + 128 * 40) * 2;   // 61440 (QK fp16, 3-stage)
    const int SM_NN128 = 3 * (128 * 40 + 32 * 136) * 2;   // 56832 (PV fp16, 3-stage)
    cudaFuncSetAttribute(mma_gemm<128, 96, 1, 2>,
                         cudaFuncAttributeMaxDynamicSharedMemorySize, SM_NT96);
    cudaFuncSetAttribute(hmma_gemm<false, 2>,
                         cudaFuncAttributeMaxDynamicSharedMemorySize, SM_NT128);
    cudaFuncSetAttribute(hmma_gemm<true, 1>,
                         cudaFuncAttributeMaxDynamicSharedMemorySize, SM_NN128);
    cudaFuncSetAttribute(mma_gemm<128, 96, 4, 0>,
                         cudaFuncAttributeMaxDynamicSharedMemorySize, SM_NT96);
    cudaFuncSetAttribute(mma_gemm<128, 96, 2, 1>,
                         cudaFuncAttributeMaxDynamicSharedMemorySize, SM_NT96);
    cudaFuncSetAttribute(mma_gemm<128, 96, 3, 0>,
                         cudaFuncAttributeMaxDynamicSharedMemorySize, SM_NT96);

    f2bf_all<<<(W_TOT + 255)/256, 256>>>(qkv_w, proj_w, fc1_w, fc2_w, p_w);

    // 1. LN1
    ln_kernel<<<LT / 8, 256>>>(x, ln1_g, ln1_b, p_ln1);

    // 2. QKV -> fp16 [N, B_, 3C] flat
    mma_gemm<128, 96, 1, 2><<<dim3(3, LT / 128, 1), 256, SM_NT96>>>(
        p_ln1, CD, p_w + W_QKV, CD, qkv_b, nullptr, p_qkv, 3 * CD, CD, 1.0f,
        nullptr, nullptr, nullptr);

    // 3. Logits: S[h] = scale * Q[h] @ K[h]^T  (fp16 acc, fp16 out)
    hmma_gemm<false, 2><<<dim3(NS / 128, NS / 128, NHD), 256, SM_NT128>>>(
        p_qkv, 3 * CD * 48, DA, p_qkv + 3 * DA, 3 * CD * 48, DA,
        p_S, NS, (long)NS * NS, DA, QK_SCALE);

    // 4. Softmax fp16 -> fp16 probs
    softmax_kernel<<<NHD * NS, 256>>>(p_S, p_P);

    // 5. O[h] = P[h] @ V[h] (NN, fp16 acc) -> bf16 g_O[n*4608 + h*1536 + d]
    hmma_gemm<true, 1><<<dim3(DA / 128, NS / 128, NHD), 256, SM_NN128>>>(
        p_P, NS, (long)NS * NS, p_qkv + 6 * DA, 3 * CD * 48, DA,
        p_O, NHD * DA, DA, NS, 1.0f);

    // 6. proj + bias + residual(x) -> fp32 g_x2  AND fused LN2 -> bf16 g_ln2
    mma_gemm<128, 96, 4, 0><<<dim3(1, LT / 128, 1), 256, SM_NT96>>>(
        p_O, CD, p_w + W_PROJ, CD, proj_b, x, p_x2, CD, CD, 1.0f,
        ln2_g, ln2_b, p_ln2);

    // 7. fc1 + bias + GELU
    mma_gemm<128, 96, 2, 1><<<dim3(HIDD / 96, LT / 128, 1), 256, SM_NT96>>>(
        p_ln2, CD, p_w + W_FC1, CD, fc1_b, nullptr, p_hid, HIDD, CD, 1.0f,
        nullptr, nullptr, nullptr);

    // 8. fc2 + bias + residual
    mma_gemm<128, 96, 3, 0><<<dim3(1, LT / 128, 1), 256, SM_NT96>>>(
        p_hid, HIDD, p_w + W_FC2, HIDD, fc2_b, p_x2, out, CD, HIDD, 1.0f,
        nullptr, nullptr, nullptr);
}